// round 7
// baseline (speedup 1.0000x reference)
#include <cuda_runtime.h>

// Problem constants
#define B_    8
#define K_    64
#define L_    1024
#define CP_   32
#define CSA_  16
#define NOC1  256
#define K1    576          // K_*G2_
#define WPAD  264          // padded smem row (floats): conflict-free transposed STS, 16B-aligned rows

typedef unsigned long long ull;

// Packed fp32x2 helpers (sm_100+)
#define FFMA2(acc, a, b) asm("fma.rn.f32x2 %0, %1, %2, %0;" : "+l"(acc) : "l"(a), "l"(b))
#define PACK2(dst, f)    asm("mov.b64 %0, {%1, %1};" : "=l"(dst) : "f"(f))
#define UNPACK2(lo, hi, v) asm("mov.b64 {%0, %1}, %2;" : "=f"(lo), "=f"(hi) : "l"(v))

// Scratch (allocation-free: device global)
__device__ float g_yq[B_ * L_ * NOC1];      // squashed conv1 output [B, L, 256]

// ---------------------------------------------------------------------------
// Kernel 1: conv1 (implicit GEMM, 'SAME') + bias + squash.
// 256 threads, 32 l x 256 oc per block (256 blocks). Thread: 2l x 16oc, FFMA2.
// Weights read directly from w1 with warp-coalesced chunk loads, transposed
// into double-buffered smem; LDG prefetch overlaps compute; 1 bar per chunk.
// ---------------------------------------------------------------------------
__global__ __launch_bounds__(256) void conv1_squash_kernel(
    const float* __restrict__ x, const float* __restrict__ w1,
    const float* __restrict__ b1)
{
    __shared__ float xs[K_][40];            // 64 ic x (32 + 8 halo)
    __shared__ float wbuf[2][16][WPAD];     // double-buffered transposed chunks
    float* ysh = &wbuf[0][0][0];            // epilogue alias, row stride WPAD
    __shared__ float b1s[NOC1];

    const int b  = blockIdx.y;
    const int l0 = blockIdx.x * 32;
    const int t  = threadIdx.x;

    b1s[t] = b1[t];
    for (int i = t; i < K_ * 40; i += 256) {
        int ic = i / 40, jj = i - ic * 40;
        int l = l0 - 4 + jj;
        xs[ic][jj] = (l >= 0 && l < L_) ? x[(b * K_ + ic) * L_ + l] : 0.f;
    }

    // chunk-load addressing: thread covers oc = (t>>2) + 64p, k-part (t&3)
    const int oc_b = t >> 2;
    const int kp   = t & 3;

    // preload chunk 0
    float4 wr[4];
#pragma unroll
    for (int p = 0; p < 4; p++)
        wr[p] = *(const float4*)(w1 + (size_t)(oc_b + 64 * p) * K1 + kp * 4);
#pragma unroll
    for (int p = 0; p < 4; p++) {
        wbuf[0][kp * 4 + 0][oc_b + 64 * p] = wr[p].x;
        wbuf[0][kp * 4 + 1][oc_b + 64 * p] = wr[p].y;
        wbuf[0][kp * 4 + 2][oc_b + 64 * p] = wr[p].z;
        wbuf[0][kp * 4 + 3][oc_b + 64 * p] = wr[p].w;
    }

    ull acc2[2][8];
#pragma unroll
    for (int j = 0; j < 2; j++)
#pragma unroll
        for (int i = 0; i < 8; i++) acc2[j][i] = 0ULL;

    const int lg = t >> 4;   // 0..15 -> l = lg*2 + {0,1}
    const int og = t & 15;   // oc = og*4 + q*64 + {0..3}
    __syncthreads();

    const int NCH = K1 / 16;  // 36
    for (int c = 0; c < NCH; c++) {
        const int cur = c & 1;
        if (c + 1 < NCH) {
#pragma unroll
            for (int p = 0; p < 4; p++)
                wr[p] = *(const float4*)(w1 + (size_t)(oc_b + 64 * p) * K1
                                         + (c + 1) * 16 + kp * 4);
        }
#pragma unroll
        for (int kk = 0; kk < 16; kk++) {
            int k  = c * 16 + kk;
            int ic = k / 9;
            int tt = k - ic * 9;
            float xv0 = xs[ic][lg * 2 + tt];
            float xv1 = xs[ic][lg * 2 + 1 + tt];
            ull X0, X1;
            PACK2(X0, xv0);
            PACK2(X1, xv1);
#pragma unroll
            for (int q = 0; q < 4; q++) {
                ulonglong2 wq = *(const ulonglong2*)&wbuf[cur][kk][og * 4 + q * 64];
                FFMA2(acc2[0][q * 2 + 0], X0, wq.x);
                FFMA2(acc2[0][q * 2 + 1], X0, wq.y);
                FFMA2(acc2[1][q * 2 + 0], X1, wq.x);
                FFMA2(acc2[1][q * 2 + 1], X1, wq.y);
            }
        }
        if (c + 1 < NCH) {
#pragma unroll
            for (int p = 0; p < 4; p++) {
                wbuf[cur ^ 1][kp * 4 + 0][oc_b + 64 * p] = wr[p].x;
                wbuf[cur ^ 1][kp * 4 + 1][oc_b + 64 * p] = wr[p].y;
                wbuf[cur ^ 1][kp * 4 + 2][oc_b + 64 * p] = wr[p].z;
                wbuf[cur ^ 1][kp * 4 + 3][oc_b + 64 * p] = wr[p].w;
            }
        }
        __syncthreads();
    }

    // Epilogue: two passes of 16 l through ysh (aliases wbuf), squash, store.
#pragma unroll
    for (int pass = 0; pass < 2; pass++) {
        if ((lg >> 3) == pass) {
            int lb = (lg & 7) * 2;
#pragma unroll
            for (int j = 0; j < 2; j++)
#pragma unroll
                for (int q = 0; q < 4; q++)
#pragma unroll
                    for (int h = 0; h < 2; h++) {
                        float lo, hi;
                        UNPACK2(lo, hi, acc2[j][q * 2 + h]);
                        int oc = og * 4 + q * 64 + h * 2;
                        ysh[(lb + j) * WPAD + oc]     = lo + b1s[oc];
                        ysh[(lb + j) * WPAD + oc + 1] = hi + b1s[oc + 1];
                    }
        }
        __syncthreads();
        for (int g = t; g < 512; g += 256) {
            int l_loc = g >> 5, cp = g & 31;
            float4 a = *(const float4*)&ysh[l_loc * WPAD + cp * 8];
            float4 c = *(const float4*)&ysh[l_loc * WPAD + cp * 8 + 4];
            float sq = a.x * a.x + a.y * a.y + a.z * a.z + a.w * a.w
                     + c.x * c.x + c.y * c.y + c.z * c.z + c.w * c.w;
            float scale = sq / (1.f + sq) * rsqrtf(sq + 1e-8f);
            a.x *= scale; a.y *= scale; a.z *= scale; a.w *= scale;
            c.x *= scale; c.y *= scale; c.z *= scale; c.w *= scale;
            int l = l0 + pass * 16 + l_loc;
            float* dst = &g_yq[((size_t)(b * L_ + l)) * NOC1 + cp * 8];
            *(float4*)dst       = a;
            *(float4*)(dst + 4) = c;
        }
        __syncthreads();
    }
}

// ---------------------------------------------------------------------------
// Kernel 2: conv2 + 3-iter routing, tuned for OCCUPANCY (4 CTAs/SM target).
// 256 threads, thread = oc = (csa, asa). dh-outer V-compute keeps only 8
// packed weights live -> low regs. Parallel softmax, butterfly b-update.
// ---------------------------------------------------------------------------
__global__ __launch_bounds__(256, 4) void conv2_route_kernel(
    const float* __restrict__ w2, const float* __restrict__ b2,
    float* __restrict__ out)
{
    __shared__ float yq3[3][NOC1];
    __shared__ float bf[512];       // routing logits [cp][csa]
    __shared__ float ef[512];       // exp(logits)
    __shared__ float sinv[CP_];     // 1/rowsum

    const int bl = blockIdx.x;
    const int l  = bl & (L_ - 1);
    const int t  = threadIdx.x;

    const float* base = g_yq + (size_t)bl * NOC1;
    yq3[1][t] = base[t];
    yq3[0][t] = (l > 0)      ? base[t - NOC1] : 0.f;
    yq3[2][t] = (l < L_ - 1) ? base[t + NOC1] : 0.f;

    bf[t]       = 0.f;
    bf[t + 256] = 0.f;
    __syncthreads();

    // V[cp], dh-outer: per dh only 4 packed weight ulls live.
    float V[CP_];
    {
        const float bias = b2[t];
#pragma unroll
        for (int cp = 0; cp < CP_; cp++) V[cp] = bias;
        const float2* wrow = (const float2*)(w2 + t * 24);
#pragma unroll
        for (int dh = 0; dh < 3; dh++) {
            ull wd[4];
#pragma unroll
            for (int h = 0; h < 4; h++) {
                float2 wv = wrow[dh * 4 + h];
                asm("mov.b64 %0, {%1, %2};" : "=l"(wd[h]) : "f"(wv.x), "f"(wv.y));
            }
#pragma unroll
            for (int cp = 0; cp < CP_; cp++) {
                const ulonglong2* yp = (const ulonglong2*)&yq3[dh][cp * 8];
                ulonglong2 ya = yp[0];
                ulonglong2 yb = yp[1];
                ull acc = 0ULL;
                FFMA2(acc, ya.x, wd[0]);
                FFMA2(acc, ya.y, wd[1]);
                FFMA2(acc, yb.x, wd[2]);
                FFMA2(acc, yb.y, wd[3]);
                float lo, hi;
                UNPACK2(lo, hi, acc);
                V[cp] += lo + hi;
            }
        }
    }

    const int csa = t >> 4;
    const int asa = t & 15;
    float v = 0.f;

    for (int r = 0; r < 3; r++) {
        float s;
        if (r == 0) {
            s = 0.f;
#pragma unroll
            for (int cp = 0; cp < CP_; cp++) s += V[cp];
            s *= (1.f / 16.f);
        } else {
            ef[t]       = __expf(bf[t]);
            ef[t + 256] = __expf(bf[t + 256]);
            __syncthreads();
            if (t < CP_) {
                float sum = 0.f;
#pragma unroll
                for (int j2 = 0; j2 < CSA_; j2++) sum += ef[t * 16 + j2];
                sinv[t] = 1.f / sum;
            }
            __syncthreads();
            s = 0.f;
#pragma unroll
            for (int cp = 0; cp < CP_; cp++)
                s += ef[cp * 16 + csa] * (sinv[cp] * V[cp]);
        }

        // squash over asa (16 contiguous lanes)
        float sq = s * s;
        sq += __shfl_xor_sync(0xffffffffu, sq, 1);
        sq += __shfl_xor_sync(0xffffffffu, sq, 2);
        sq += __shfl_xor_sync(0xffffffffu, sq, 4);
        sq += __shfl_xor_sync(0xffffffffu, sq, 8);
        float scale = sq / (1.f + sq) * rsqrtf(sq + 1e-8f);
        v = s * scale;

        if (r < 2) {
            // a[cp][csa] = sum_asa V*v via multi-value butterfly (30 shfl).
            float val[16];
            {
                bool u = (asa & 1);
#pragma unroll
                for (int i = 0; i < 16; i++) {
                    float sp = (u ? V[i] : V[16 + i]) * v;
                    float kp = (u ? V[16 + i] : V[i]) * v;
                    val[i] = kp + __shfl_xor_sync(0xffffffffu, sp, 1);
                }
            }
            {
                bool u = (asa & 2);
#pragma unroll
                for (int i = 0; i < 8; i++) {
                    float sp = u ? val[i] : val[8 + i];
                    float kp = u ? val[8 + i] : val[i];
                    val[i] = kp + __shfl_xor_sync(0xffffffffu, sp, 2);
                }
            }
            {
                bool u = (asa & 4);
#pragma unroll
                for (int i = 0; i < 4; i++) {
                    float sp = u ? val[i] : val[4 + i];
                    float kp = u ? val[4 + i] : val[i];
                    val[i] = kp + __shfl_xor_sync(0xffffffffu, sp, 4);
                }
            }
            {
                bool u = (asa & 8);
#pragma unroll
                for (int i = 0; i < 2; i++) {
                    float sp = u ? val[i] : val[2 + i];
                    float kp = u ? val[2 + i] : val[i];
                    val[i] = kp + __shfl_xor_sync(0xffffffffu, sp, 8);
                }
            }
            int c0 = ((asa & 1) << 4) | ((asa & 2) << 2) | (asa & 4) | ((asa & 8) >> 2);
            bf[c0 * 16 + csa]       += val[0];
            bf[(c0 + 1) * 16 + csa] += val[1];
            __syncthreads();
        }
    }

    out[(size_t)bl * 256 + t] = v;
}

// ---------------------------------------------------------------------------
extern "C" void kernel_launch(void* const* d_in, const int* in_sizes, int n_in,
                              void* d_out, int out_size)
{
    const float* x  = (const float*)d_in[0];   // [8, 64, 1024]
    const float* w1 = (const float*)d_in[1];   // [256, 64, 9]
    const float* b1 = (const float*)d_in[2];   // [256]
    const float* w2 = (const float*)d_in[3];   // [256, 1, 3, 8]
    const float* b2 = (const float*)d_in[4];   // [256]
    float* out = (float*)d_out;                // [8, 16384, 16]

    conv1_squash_kernel<<<dim3(L_ / 32, B_), 256>>>(x, w1, b1);
    conv2_route_kernel<<<B_ * L_, 256>>>(w2, b2, out);
}

// round 8
// speedup vs baseline: 1.0059x; 1.0059x over previous
#include <cuda_runtime.h>

// Problem constants
#define B_    8
#define K_    64
#define L_    1024
#define CP_   32
#define CSA_  16
#define NOC1  256
#define K1    576          // K_*G2_

typedef unsigned long long ull;

// Packed fp32x2 helpers (sm_100+)
#define FFMA2(acc, a, b) asm("fma.rn.f32x2 %0, %1, %2, %0;" : "+l"(acc) : "l"(a), "l"(b))
#define PACK2(dst, f)    asm("mov.b64 %0, {%1, %1};" : "=l"(dst) : "f"(f))
#define UNPACK2(lo, hi, v) asm("mov.b64 {%0, %1}, %2;" : "=f"(lo), "=f"(hi) : "l"(v))

// Scratch (allocation-free: device globals)
__device__ float g_yq[B_ * L_ * NOC1];      // squashed conv1 output [B, L, 256]
__device__ float g_wT[K1 * NOC1];           // conv1 weights transposed [k][oc]

// ---------------------------------------------------------------------------
// Prep: transpose conv1 weights for coalesced streaming
// ---------------------------------------------------------------------------
__global__ void prep_kernel(const float* __restrict__ w1) {
    int idx = blockIdx.x * 256 + threadIdx.x;
    if (idx < K1 * NOC1) {
        int k = idx >> 8, oc = idx & 255;
        g_wT[idx] = w1[oc * K1 + k];
    }
}

// ---------------------------------------------------------------------------
// Kernel 1: conv1 (implicit GEMM, 'SAME') + bias + squash. FFMA2 inner loop.
// Block: 16 l x 256 oc, 128 threads. Thread: 2l x 16oc. Grid: 512 blocks.
// (measured-best R3 shape)
// ---------------------------------------------------------------------------
__global__ __launch_bounds__(128) void conv1_squash_kernel(
    const float* __restrict__ x, const float* __restrict__ b1)
{
    __shared__ float xs[K_][24];      // 64 ic x (16 + 8 halo)
    __shared__ float ws[16][NOC1];    // weight chunk (16 k rows)
    __shared__ float ysh[16][NOC1];   // staging for squash
    __shared__ float b1s[NOC1];

    const int b  = blockIdx.y;
    const int l0 = blockIdx.x * 16;
    const int t  = threadIdx.x;

    b1s[t]       = b1[t];
    b1s[t + 128] = b1[t + 128];
    for (int i = t; i < K_ * 24; i += 128) {
        int ic = i / 24, jj = i - ic * 24;
        int l = l0 - 4 + jj;
        xs[ic][jj] = (l >= 0 && l < L_) ? x[(b * K_ + ic) * L_ + l] : 0.f;
    }

    ull acc2[2][8];
#pragma unroll
    for (int j = 0; j < 2; j++)
#pragma unroll
        for (int i = 0; i < 8; i++) acc2[j][i] = 0ULL;

    const int lg = t >> 4;   // 0..7 -> l = lg*2 + {0,1}
    const int og = t & 15;   // oc = og*4 + q*64 + {0..3}
    __syncthreads();

    const float4* wT4 = (const float4*)g_wT;
    for (int kc = 0; kc < K1; kc += 16) {
#pragma unroll
        for (int i = 0; i < 8; i++)
            ((float4*)ws)[t + i * 128] = wT4[kc * 64 + t + i * 128];
        __syncthreads();
#pragma unroll
        for (int kk = 0; kk < 16; kk++) {
            int k  = kc + kk;
            int ic = k / 9;
            int tt = k - ic * 9;
            float xv0 = xs[ic][lg * 2 + tt];
            float xv1 = xs[ic][lg * 2 + 1 + tt];
            ull X0, X1;
            PACK2(X0, xv0);
            PACK2(X1, xv1);
#pragma unroll
            for (int q = 0; q < 4; q++) {
                ulonglong2 wq = *(const ulonglong2*)&ws[kk][og * 4 + q * 64];
                FFMA2(acc2[0][q * 2 + 0], X0, wq.x);
                FFMA2(acc2[0][q * 2 + 1], X0, wq.y);
                FFMA2(acc2[1][q * 2 + 0], X1, wq.x);
                FFMA2(acc2[1][q * 2 + 1], X1, wq.y);
            }
        }
        __syncthreads();
    }

    // Epilogue: stage y+bias, squash per 8-group, write g_yq
#pragma unroll
    for (int j = 0; j < 2; j++)
#pragma unroll
        for (int q = 0; q < 4; q++)
#pragma unroll
            for (int h = 0; h < 2; h++) {
                float lo, hi;
                UNPACK2(lo, hi, acc2[j][q * 2 + h]);
                int oc = og * 4 + q * 64 + h * 2;
                ysh[lg * 2 + j][oc]     = lo + b1s[oc];
                ysh[lg * 2 + j][oc + 1] = hi + b1s[oc + 1];
            }
    __syncthreads();
#pragma unroll
    for (int g = t; g < 512; g += 128) {
        int l_loc = g >> 5, cp = g & 31;
        float4 a = *(const float4*)&ysh[l_loc][cp * 8];
        float4 c = *(const float4*)&ysh[l_loc][cp * 8 + 4];
        float sq = a.x * a.x + a.y * a.y + a.z * a.z + a.w * a.w
                 + c.x * c.x + c.y * c.y + c.z * c.z + c.w * c.w;
        float scale = sq / (1.f + sq) * rsqrtf(sq + 1e-8f);
        a.x *= scale; a.y *= scale; a.z *= scale; a.w *= scale;
        c.x *= scale; c.y *= scale; c.z *= scale; c.w *= scale;
        int l = l0 + l_loc;
        float* dst = &g_yq[((size_t)(b * L_ + l)) * NOC1 + cp * 8];
        *(float4*)dst       = a;
        *(float4*)(dst + 4) = c;
    }
}

// ---------------------------------------------------------------------------
// Kernel 2: conv2 + 3-iter routing, instruction-minimized.
// Thread t = oc = (csa=t>>4, asa=t&15). V[32] in regs via dh-inner FFMA2 with
// preloaded packed weights. Softmax coefficients prenormalized + transposed
// (csnT) so the s-loop is 8x LDS.128. Butterfly b-update (30 shfl).
// ---------------------------------------------------------------------------
__global__ __launch_bounds__(256) void conv2_route_kernel(
    const float* __restrict__ w2, const float* __restrict__ b2,
    float* __restrict__ out)
{
    __shared__ float ypk[CP_][24];      // y per cp: [cp][dh*8+j]
    __shared__ float bf[512];           // routing logits, flat cp*16+csa
    __shared__ float efm[CP_][20];      // exp(logits), padded rows
    __shared__ float csnT[16][36];      // normalized coeffs transposed [csa][cp]

    const int bl = blockIdx.x;
    const int l  = bl & (L_ - 1);
    const int t  = threadIdx.x;

    // y rows -> per-cp packed layout
    {
        const float* base = g_yq + (size_t)bl * NOC1;
        const int cp_i = t >> 3, j_i = t & 7;
        ypk[cp_i][8  + j_i] = base[t];
        ypk[cp_i][0  + j_i] = (l > 0)      ? base[t - NOC1] : 0.f;
        ypk[cp_i][16 + j_i] = (l < L_ - 1) ? base[t + NOC1] : 0.f;
    }
    bf[t]       = 0.f;
    bf[t + 256] = 0.f;

    // packed conv2 weights (contiguous row of 24 floats)
    ull w2p[12];
    {
        const float2* wrow = (const float2*)(w2 + t * 24);
#pragma unroll
        for (int h = 0; h < 12; h++) {
            float2 wv = wrow[h];
            asm("mov.b64 %0, {%1, %2};" : "=l"(w2p[h]) : "f"(wv.x), "f"(wv.y));
        }
    }
    const float bias = b2[t];
    __syncthreads();

    // V[cp]: 6 LDS.128 + 12 FFMA2 + 1 unpack per cp
    float V[CP_];
#pragma unroll
    for (int cp = 0; cp < CP_; cp++) {
        ull acc;
        asm("mov.b64 %0, {%1, %2};" : "=l"(acc) : "f"(bias), "f"(0.f));
        const ulonglong2* yp = (const ulonglong2*)ypk[cp];
        ulonglong2 y0 = yp[0], y1 = yp[1], y2 = yp[2];
        FFMA2(acc, y0.x, w2p[0]);
        FFMA2(acc, y0.y, w2p[1]);
        FFMA2(acc, y1.x, w2p[2]);
        FFMA2(acc, y1.y, w2p[3]);
        FFMA2(acc, y2.x, w2p[4]);
        FFMA2(acc, y2.y, w2p[5]);
        ulonglong2 y3 = yp[3], y4 = yp[4], y5 = yp[5];
        FFMA2(acc, y3.x, w2p[6]);
        FFMA2(acc, y3.y, w2p[7]);
        FFMA2(acc, y4.x, w2p[8]);
        FFMA2(acc, y4.y, w2p[9]);
        FFMA2(acc, y5.x, w2p[10]);
        FFMA2(acc, y5.y, w2p[11]);
        float lo, hi;
        UNPACK2(lo, hi, acc);
        V[cp] = lo + hi;
    }

    const int csa = t >> 4;
    const int asa = t & 15;
    float v = 0.f;

    for (int r = 0; r < 3; r++) {
        float s;
        if (r == 0) {
            s = 0.f;
#pragma unroll
            for (int cp = 0; cp < CP_; cp++) s += V[cp];
            s *= (1.f / 16.f);
        } else {
            // exp into padded [cp][20] rows
            {
                int e0 = t, e1 = t + 256;
                efm[e0 >> 4][e0 & 15] = __expf(bf[e0]);
                efm[e1 >> 4][e1 & 15] = __expf(bf[e1]);
            }
            __syncthreads();
            // csnT[csa][cp] = ef/rowsum; thread handles (csa1, cp_m) and (csa1+8, cp_m)
            {
                const int cp_m = t & 31;
                const int csa1 = t >> 5;                 // 0..7
                const float4* ep = (const float4*)efm[cp_m];
                float4 a0 = ep[0], a1 = ep[1], a2 = ep[2], a3 = ep[3];
                float sum = a0.x + a0.y + a0.z + a0.w + a1.x + a1.y + a1.z + a1.w
                          + a2.x + a2.y + a2.z + a2.w + a3.x + a3.y + a3.z + a3.w;
                float inv = __fdividef(1.f, sum);
                csnT[csa1][cp_m]     = efm[cp_m][csa1] * inv;
                csnT[csa1 + 8][cp_m] = efm[cp_m][csa1 + 8] * inv;
            }
            __syncthreads();
            // s = sum_cp csnT[csa][cp] * V[cp]  (8 LDS.128)
            s = 0.f;
            const float4* cv = (const float4*)csnT[csa];
#pragma unroll
            for (int q = 0; q < 8; q++) {
                float4 c4 = cv[q];
                s += c4.x * V[q * 4 + 0] + c4.y * V[q * 4 + 1]
                   + c4.z * V[q * 4 + 2] + c4.w * V[q * 4 + 3];
            }
        }

        // squash over asa (16 contiguous lanes)
        float sq = s * s;
        sq += __shfl_xor_sync(0xffffffffu, sq, 1);
        sq += __shfl_xor_sync(0xffffffffu, sq, 2);
        sq += __shfl_xor_sync(0xffffffffu, sq, 4);
        sq += __shfl_xor_sync(0xffffffffu, sq, 8);
        float scale = sq / (1.f + sq) * rsqrtf(sq + 1e-8f);
        v = s * scale;

        if (r < 2) {
            // a[cp][csa] = sum_asa V*v via multi-value butterfly (30 shfl).
            float val[16];
            {
                bool u = (asa & 1);
#pragma unroll
                for (int i = 0; i < 16; i++) {
                    float sp = (u ? V[i] : V[16 + i]) * v;
                    float kp = (u ? V[16 + i] : V[i]) * v;
                    val[i] = kp + __shfl_xor_sync(0xffffffffu, sp, 1);
                }
            }
            {
                bool u = (asa & 2);
#pragma unroll
                for (int i = 0; i < 8; i++) {
                    float sp = u ? val[i] : val[8 + i];
                    float kp = u ? val[8 + i] : val[i];
                    val[i] = kp + __shfl_xor_sync(0xffffffffu, sp, 2);
                }
            }
            {
                bool u = (asa & 4);
#pragma unroll
                for (int i = 0; i < 4; i++) {
                    float sp = u ? val[i] : val[4 + i];
                    float kp = u ? val[4 + i] : val[i];
                    val[i] = kp + __shfl_xor_sync(0xffffffffu, sp, 4);
                }
            }
            {
                bool u = (asa & 8);
#pragma unroll
                for (int i = 0; i < 2; i++) {
                    float sp = u ? val[i] : val[2 + i];
                    float kp = u ? val[2 + i] : val[i];
                    val[i] = kp + __shfl_xor_sync(0xffffffffu, sp, 8);
                }
            }
            int c0 = ((asa & 1) << 4) | ((asa & 2) << 2) | (asa & 4) | ((asa & 8) >> 2);
            bf[c0 * 16 + csa]       += val[0];
            bf[(c0 + 1) * 16 + csa] += val[1];
            __syncthreads();
        }
    }

    out[(size_t)bl * 256 + t] = v;
}

// ---------------------------------------------------------------------------
extern "C" void kernel_launch(void* const* d_in, const int* in_sizes, int n_in,
                              void* d_out, int out_size)
{
    const float* x  = (const float*)d_in[0];   // [8, 64, 1024]
    const float* w1 = (const float*)d_in[1];   // [256, 64, 9]
    const float* b1 = (const float*)d_in[2];   // [256]
    const float* w2 = (const float*)d_in[3];   // [256, 1, 3, 8]
    const float* b2 = (const float*)d_in[4];   // [256]
    float* out = (float*)d_out;                // [8, 16384, 16]

    prep_kernel<<<576, 256>>>(w1);
    conv1_squash_kernel<<<dim3(L_ / 16, B_), 128>>>(x, b1);
    conv2_route_kernel<<<B_ * L_, 256>>>(w2, b2, out);
}

// round 9
// speedup vs baseline: 1.0851x; 1.0787x over previous
#include <cuda_runtime.h>

// Problem constants
#define B_    8
#define K_    64
#define L_    1024
#define CP_   32
#define CSA_  16
#define NOC1  256
#define K1    576          // K_*G2_
#define VPAD  40           // Vs cp-dim pad: 160B rows (16B aligned), near-conflict-free

typedef unsigned long long ull;

// Packed fp32x2 helpers (sm_100+)
#define FFMA2(acc, a, b) asm("fma.rn.f32x2 %0, %1, %2, %0;" : "+l"(acc) : "l"(a), "l"(b))
#define PACK2(dst, f)    asm("mov.b64 %0, {%1, %1};" : "=l"(dst) : "f"(f))
#define UNPACK2(lo, hi, v) asm("mov.b64 {%0, %1}, %2;" : "=f"(lo), "=f"(hi) : "l"(v))

// Scratch (allocation-free: device globals)
__device__ float g_yq[B_ * L_ * NOC1];      // squashed conv1 output [B, L, 256]
__device__ float g_wT[K1 * NOC1];           // conv1 weights transposed [k][oc]

// ---------------------------------------------------------------------------
// Prep: transpose conv1 weights for coalesced streaming
// ---------------------------------------------------------------------------
__global__ void prep_kernel(const float* __restrict__ w1) {
    int idx = blockIdx.x * 256 + threadIdx.x;
    if (idx < K1 * NOC1) {
        int k = idx >> 8, oc = idx & 255;
        g_wT[idx] = w1[oc * K1 + k];
    }
}

// ---------------------------------------------------------------------------
// Kernel 1: conv1 (implicit GEMM, 'SAME') + bias + squash. FFMA2 inner loop.
// Block: 16 l x 256 oc, 128 threads. Thread: 2l x 16oc. Grid: 512 blocks.
// wsh aliased: weight chunk during mainloop, squash staging in epilogue.
// smem 23KB -> ~8 CTAs/SM.
// ---------------------------------------------------------------------------
__global__ __launch_bounds__(128) void conv1_squash_kernel(
    const float* __restrict__ x, const float* __restrict__ b1)
{
    __shared__ float xs[K_][24];      // 64 ic x (16 + 8 halo)
    __shared__ float wsh[16][NOC1];   // weight chunk / epilogue staging (aliased)
    __shared__ float b1s[NOC1];

    const int b  = blockIdx.y;
    const int l0 = blockIdx.x * 16;
    const int t  = threadIdx.x;

    b1s[t]       = b1[t];
    b1s[t + 128] = b1[t + 128];
    for (int i = t; i < K_ * 24; i += 128) {
        int ic = i / 24, jj = i - ic * 24;
        int l = l0 - 4 + jj;
        xs[ic][jj] = (l >= 0 && l < L_) ? x[(b * K_ + ic) * L_ + l] : 0.f;
    }

    ull acc2[2][8];
#pragma unroll
    for (int j = 0; j < 2; j++)
#pragma unroll
        for (int i = 0; i < 8; i++) acc2[j][i] = 0ULL;

    const int lg = t >> 4;   // 0..7 -> l = lg*2 + {0,1}
    const int og = t & 15;   // oc = og*4 + q*64 + {0..3}
    __syncthreads();

    const float4* wT4 = (const float4*)g_wT;
    for (int kc = 0; kc < K1; kc += 16) {
#pragma unroll
        for (int i = 0; i < 8; i++)
            ((float4*)wsh)[t + i * 128] = wT4[kc * 64 + t + i * 128];
        __syncthreads();
#pragma unroll
        for (int kk = 0; kk < 16; kk++) {
            int k  = kc + kk;
            int ic = k / 9;
            int tt = k - ic * 9;
            float xv0 = xs[ic][lg * 2 + tt];
            float xv1 = xs[ic][lg * 2 + 1 + tt];
            ull X0, X1;
            PACK2(X0, xv0);
            PACK2(X1, xv1);
#pragma unroll
            for (int q = 0; q < 4; q++) {
                ulonglong2 wq = *(const ulonglong2*)&wsh[kk][og * 4 + q * 64];
                FFMA2(acc2[0][q * 2 + 0], X0, wq.x);
                FFMA2(acc2[0][q * 2 + 1], X0, wq.y);
                FFMA2(acc2[1][q * 2 + 0], X1, wq.x);
                FFMA2(acc2[1][q * 2 + 1], X1, wq.y);
            }
        }
        __syncthreads();
    }

    // Epilogue: stage y+bias into wsh (weights no longer needed), squash, store
#pragma unroll
    for (int j = 0; j < 2; j++)
#pragma unroll
        for (int q = 0; q < 4; q++)
#pragma unroll
            for (int h = 0; h < 2; h++) {
                float lo, hi;
                UNPACK2(lo, hi, acc2[j][q * 2 + h]);
                int oc = og * 4 + q * 64 + h * 2;
                wsh[lg * 2 + j][oc]     = lo + b1s[oc];
                wsh[lg * 2 + j][oc + 1] = hi + b1s[oc + 1];
            }
    __syncthreads();
#pragma unroll
    for (int g = t; g < 512; g += 128) {
        int l_loc = g >> 5, cp = g & 31;
        float4 a = *(const float4*)&wsh[l_loc][cp * 8];
        float4 c = *(const float4*)&wsh[l_loc][cp * 8 + 4];
        float sq = a.x * a.x + a.y * a.y + a.z * a.z + a.w * a.w
                 + c.x * c.x + c.y * c.y + c.z * c.z + c.w * c.w;
        float scale = sq / (1.f + sq) * rsqrtf(sq + 1e-8f);
        a.x *= scale; a.y *= scale; a.z *= scale; a.w *= scale;
        c.x *= scale; c.y *= scale; c.z *= scale; c.w *= scale;
        int l = l0 + l_loc;
        float* dst = &g_yq[((size_t)(b * L_ + l)) * NOC1 + cp * 8];
        *(float4*)dst       = a;
        *(float4*)(dst + 4) = c;
    }
}

// ---------------------------------------------------------------------------
// Kernel 2: conv2 + 3-iter routing, NO butterfly.
// V kept in regs (s-phase) AND mirrored once to smem Vs[csa][asa][cp] so the
// b-update is a serial per-thread dot over asa. Routing logits b live in 2
// registers per thread (thread t owns pairs (cp=t&31, csa=t>>5 and +8)).
// ---------------------------------------------------------------------------
__global__ __launch_bounds__(256) void conv2_route_kernel(
    const float* __restrict__ w2, const float* __restrict__ b2,
    float* __restrict__ out)
{
    __shared__ float yq3[3][NOC1];          // rows l-1, l, l+1
    __shared__ float ef[CP_][17];           // exp(logits), padded
    __shared__ float sinv[CP_];             // 1/rowsum
    __shared__ float vsh[16][16];           // v values [csa][asa]
    __shared__ float Vs[16][16][VPAD];      // V mirror [csa][asa][cp]

    const int bl = blockIdx.x;
    const int l  = bl & (L_ - 1);
    const int t  = threadIdx.x;

    {
        const float* base = g_yq + (size_t)bl * NOC1;
        yq3[1][t] = base[t];
        yq3[0][t] = (l > 0)      ? base[t - NOC1] : 0.f;
        yq3[2][t] = (l < L_ - 1) ? base[t + NOC1] : 0.f;
    }

    // packed conv2 weights (contiguous row of 24 floats per oc)
    ull w2p[12];
    {
        const float2* wrow = (const float2*)(w2 + t * 24);
#pragma unroll
        for (int h = 0; h < 12; h++) {
            float2 wv = wrow[h];
            asm("mov.b64 %0, {%1, %2};" : "=l"(w2p[h]) : "f"(wv.x), "f"(wv.y));
        }
    }
    const float bias = b2[t];
    __syncthreads();

    // V[cp]: dh-inner, 6 LDS.128 + 12 FFMA2 + unpack per cp
    float V[CP_];
#pragma unroll
    for (int cp = 0; cp < CP_; cp++) {
        ull acc;
        asm("mov.b64 %0, {%1, %2};" : "=l"(acc) : "f"(bias), "f"(0.f));
        const ulonglong2* y0 = (const ulonglong2*)&yq3[0][cp * 8];
        const ulonglong2* y1 = (const ulonglong2*)&yq3[1][cp * 8];
        const ulonglong2* y2 = (const ulonglong2*)&yq3[2][cp * 8];
        ulonglong2 a0 = y0[0], b0v = y0[1];
        ulonglong2 a1 = y1[0], b1v = y1[1];
        ulonglong2 a2 = y2[0], b2v = y2[1];
        FFMA2(acc, a0.x, w2p[0]);
        FFMA2(acc, a0.y, w2p[1]);
        FFMA2(acc, b0v.x, w2p[2]);
        FFMA2(acc, b0v.y, w2p[3]);
        FFMA2(acc, a1.x, w2p[4]);
        FFMA2(acc, a1.y, w2p[5]);
        FFMA2(acc, b1v.x, w2p[6]);
        FFMA2(acc, b1v.y, w2p[7]);
        FFMA2(acc, a2.x, w2p[8]);
        FFMA2(acc, a2.y, w2p[9]);
        FFMA2(acc, b2v.x, w2p[10]);
        FFMA2(acc, b2v.y, w2p[11]);
        float lo, hi;
        UNPACK2(lo, hi, acc);
        V[cp] = lo + hi;
    }

    const int csa = t >> 4;
    const int asa = t & 15;

    // Mirror V to smem for the a-update phase (8 STS.128)
#pragma unroll
    for (int q = 0; q < 8; q++) {
        float4 vv = make_float4(V[q * 4], V[q * 4 + 1], V[q * 4 + 2], V[q * 4 + 3]);
        *(float4*)&Vs[csa][asa][q * 4] = vv;
    }

    // ---- r = 0: uniform softmax ----
    float v;
    {
        float s = 0.f;
#pragma unroll
        for (int cp = 0; cp < CP_; cp++) s += V[cp];
        s *= (1.f / 16.f);
        float sq = s * s;
        sq += __shfl_xor_sync(0xffffffffu, sq, 1);
        sq += __shfl_xor_sync(0xffffffffu, sq, 2);
        sq += __shfl_xor_sync(0xffffffffu, sq, 4);
        sq += __shfl_xor_sync(0xffffffffu, sq, 8);
        float scale = sq / (1.f + sq) * rsqrtf(sq + 1e-8f);
        v = s * scale;
    }
    vsh[csa][asa] = v;
    __syncthreads();   // Vs + vsh visible

    // a-update thread mapping: pairs (cp_a, cs0) and (cp_a, cs0+8)
    const int cp_a = t & 31;
    const int cs0  = t >> 5;       // 0..7
    float blog0, blog1;
    {
        const float4* vpA = (const float4*)vsh[cs0];
        const float4* vpB = (const float4*)vsh[cs0 + 8];
        float4 vA0 = vpA[0], vA1 = vpA[1], vA2 = vpA[2], vA3 = vpA[3];
        float4 vB0 = vpB[0], vB1 = vpB[1], vB2 = vpB[2], vB3 = vpB[3];
        float a0 = 0.f, a1 = 0.f;
        const float* VsA = &Vs[cs0][0][cp_a];
        const float* VsB = &Vs[cs0 + 8][0][cp_a];
        a0 += VsA[0*VPAD]*vA0.x + VsA[1*VPAD]*vA0.y + VsA[2*VPAD]*vA0.z + VsA[3*VPAD]*vA0.w;
        a0 += VsA[4*VPAD]*vA1.x + VsA[5*VPAD]*vA1.y + VsA[6*VPAD]*vA1.z + VsA[7*VPAD]*vA1.w;
        a0 += VsA[8*VPAD]*vA2.x + VsA[9*VPAD]*vA2.y + VsA[10*VPAD]*vA2.z + VsA[11*VPAD]*vA2.w;
        a0 += VsA[12*VPAD]*vA3.x + VsA[13*VPAD]*vA3.y + VsA[14*VPAD]*vA3.z + VsA[15*VPAD]*vA3.w;
        a1 += VsB[0*VPAD]*vB0.x + VsB[1*VPAD]*vB0.y + VsB[2*VPAD]*vB0.z + VsB[3*VPAD]*vB0.w;
        a1 += VsB[4*VPAD]*vB1.x + VsB[5*VPAD]*vB1.y + VsB[6*VPAD]*vB1.z + VsB[7*VPAD]*vB1.w;
        a1 += VsB[8*VPAD]*vB2.x + VsB[9*VPAD]*vB2.y + VsB[10*VPAD]*vB2.z + VsB[11*VPAD]*vB2.w;
        a1 += VsB[12*VPAD]*vB3.x + VsB[13*VPAD]*vB3.y + VsB[14*VPAD]*vB3.z + VsB[15*VPAD]*vB3.w;
        blog0 = a0;
        blog1 = a1;
    }

    // ---- r = 1, 2 ----
#pragma unroll
    for (int r = 1; r < 3; r++) {
        ef[cp_a][cs0]     = __expf(blog0);
        ef[cp_a][cs0 + 8] = __expf(blog1);
        __syncthreads();
        if (t < CP_) {
            float sum = 0.f;
#pragma unroll
            for (int j2 = 0; j2 < CSA_; j2++) sum += ef[t][j2];
            sinv[t] = __fdividef(1.f, sum);
        }
        __syncthreads();

        float s = 0.f;
#pragma unroll
        for (int cp = 0; cp < CP_; cp++)
            s += ef[cp][csa] * (sinv[cp] * V[cp]);

        float sq = s * s;
        sq += __shfl_xor_sync(0xffffffffu, sq, 1);
        sq += __shfl_xor_sync(0xffffffffu, sq, 2);
        sq += __shfl_xor_sync(0xffffffffu, sq, 4);
        sq += __shfl_xor_sync(0xffffffffu, sq, 8);
        float scale = sq / (1.f + sq) * rsqrtf(sq + 1e-8f);
        v = s * scale;

        if (r < 2) {
            vsh[csa][asa] = v;
            __syncthreads();
            const float4* vpA = (const float4*)vsh[cs0];
            const float4* vpB = (const float4*)vsh[cs0 + 8];
            float4 vA0 = vpA[0], vA1 = vpA[1], vA2 = vpA[2], vA3 = vpA[3];
            float4 vB0 = vpB[0], vB1 = vpB[1], vB2 = vpB[2], vB3 = vpB[3];
            float a0 = 0.f, a1 = 0.f;
            const float* VsA = &Vs[cs0][0][cp_a];
            const float* VsB = &Vs[cs0 + 8][0][cp_a];
            a0 += VsA[0*VPAD]*vA0.x + VsA[1*VPAD]*vA0.y + VsA[2*VPAD]*vA0.z + VsA[3*VPAD]*vA0.w;
            a0 += VsA[4*VPAD]*vA1.x + VsA[5*VPAD]*vA1.y + VsA[6*VPAD]*vA1.z + VsA[7*VPAD]*vA1.w;
            a0 += VsA[8*VPAD]*vA2.x + VsA[9*VPAD]*vA2.y + VsA[10*VPAD]*vA2.z + VsA[11*VPAD]*vA2.w;
            a0 += VsA[12*VPAD]*vA3.x + VsA[13*VPAD]*vA3.y + VsA[14*VPAD]*vA3.z + VsA[15*VPAD]*vA3.w;
            a1 += VsB[0*VPAD]*vB0.x + VsB[1*VPAD]*vB0.y + VsB[2*VPAD]*vB0.z + VsB[3*VPAD]*vB0.w;
            a1 += VsB[4*VPAD]*vB1.x + VsB[5*VPAD]*vB1.y + VsB[6*VPAD]*vB1.z + VsB[7*VPAD]*vB1.w;
            a1 += VsB[8*VPAD]*vB2.x + VsB[9*VPAD]*vB2.y + VsB[10*VPAD]*vB2.z + VsB[11*VPAD]*vB2.w;
            a1 += VsB[12*VPAD]*vB3.x + VsB[13*VPAD]*vB3.y + VsB[14*VPAD]*vB3.z + VsB[15*VPAD]*vB3.w;
            blog0 += a0;
            blog1 += a1;
        }
    }

    out[(size_t)bl * 256 + t] = v;
}

// ---------------------------------------------------------------------------
extern "C" void kernel_launch(void* const* d_in, const int* in_sizes, int n_in,
                              void* d_out, int out_size)
{
    const float* x  = (const float*)d_in[0];   // [8, 64, 1024]
    const float* w1 = (const float*)d_in[1];   // [256, 64, 9]
    const float* b1 = (const float*)d_in[2];   // [256]
    const float* w2 = (const float*)d_in[3];   // [256, 1, 3, 8]
    const float* b2 = (const float*)d_in[4];   // [256]
    float* out = (float*)d_out;                // [8, 16384, 16]

    prep_kernel<<<576, 256>>>(w1);
    conv1_squash_kernel<<<dim3(L_ / 16, B_), 128>>>(x, b1);
    conv2_route_kernel<<<B_ * L_, 256>>>(w2, b2, out);
}

// round 10
// speedup vs baseline: 1.1030x; 1.0165x over previous
#include <cuda_runtime.h>

// Problem constants
#define B_    8
#define K_    64
#define L_    1024
#define CP_   32
#define CSA_  16
#define NOC1  256
#define K1    576          // K_*G2_
#define VPAD  36           // Vs cp-dim pad (float4-aligned rows)

typedef unsigned long long ull;

// Packed fp32x2 helpers (sm_100+)
#define FFMA2(acc, a, b) asm("fma.rn.f32x2 %0, %1, %2, %0;" : "+l"(acc) : "l"(a), "l"(b))
#define PACK2(dst, f)    asm("mov.b64 %0, {%1, %1};" : "=l"(dst) : "f"(f))
#define UNPACK2(lo, hi, v) asm("mov.b64 {%0, %1}, %2;" : "=f"(lo), "=f"(hi) : "l"(v))

// Scratch (allocation-free: device globals)
__device__ float g_yq[B_ * L_ * NOC1];      // squashed conv1 output [B, L, 256]
__device__ float g_wT[K1 * NOC1];           // conv1 weights transposed [k][oc]

// ---------------------------------------------------------------------------
// Prep: transpose conv1 weights for coalesced streaming
// ---------------------------------------------------------------------------
__global__ void prep_kernel(const float* __restrict__ w1) {
    int idx = blockIdx.x * 256 + threadIdx.x;
    if (idx < K1 * NOC1) {
        int k = idx >> 8, oc = idx & 255;
        g_wT[idx] = w1[oc * K1 + k];
    }
}

// ---------------------------------------------------------------------------
// Kernel 1: conv1 (implicit GEMM, 'SAME') + bias + squash. FFMA2 inner loop.
// Block: 16 l x 256 oc, 128 threads. Thread: 2l x 16oc (16 indep accs).
// ---------------------------------------------------------------------------
__global__ __launch_bounds__(128) void conv1_squash_kernel(
    const float* __restrict__ x, const float* __restrict__ b1)
{
    __shared__ float xs[K_][24];      // 64 ic x (16 + 8 halo)
    __shared__ float wsh[16][NOC1];   // weight chunk / epilogue staging (aliased)
    __shared__ float b1s[NOC1];

    const int b  = blockIdx.y;
    const int l0 = blockIdx.x * 16;
    const int t  = threadIdx.x;

    b1s[t]       = b1[t];
    b1s[t + 128] = b1[t + 128];
    for (int i = t; i < K_ * 24; i += 128) {
        int ic = i / 24, jj = i - ic * 24;
        int l = l0 - 4 + jj;
        xs[ic][jj] = (l >= 0 && l < L_) ? x[(b * K_ + ic) * L_ + l] : 0.f;
    }

    ull acc2[2][8];
#pragma unroll
    for (int j = 0; j < 2; j++)
#pragma unroll
        for (int i = 0; i < 8; i++) acc2[j][i] = 0ULL;

    const int lg = t >> 4;   // 0..7 -> l = lg*2 + {0,1}
    const int og = t & 15;   // oc = og*4 + q*64 + {0..3}
    __syncthreads();

    const float4* wT4 = (const float4*)g_wT;
    for (int kc = 0; kc < K1; kc += 16) {
#pragma unroll
        for (int i = 0; i < 8; i++)
            ((float4*)wsh)[t + i * 128] = wT4[kc * 64 + t + i * 128];
        __syncthreads();
#pragma unroll
        for (int kk = 0; kk < 16; kk++) {
            int k  = kc + kk;
            int ic = k / 9;
            int tt = k - ic * 9;
            float xv0 = xs[ic][lg * 2 + tt];
            float xv1 = xs[ic][lg * 2 + 1 + tt];
            ull X0, X1;
            PACK2(X0, xv0);
            PACK2(X1, xv1);
#pragma unroll
            for (int q = 0; q < 4; q++) {
                ulonglong2 wq = *(const ulonglong2*)&wsh[kk][og * 4 + q * 64];
                FFMA2(acc2[0][q * 2 + 0], X0, wq.x);
                FFMA2(acc2[0][q * 2 + 1], X0, wq.y);
                FFMA2(acc2[1][q * 2 + 0], X1, wq.x);
                FFMA2(acc2[1][q * 2 + 1], X1, wq.y);
            }
        }
        __syncthreads();
    }

    // Epilogue: stage y+bias into wsh (aliased), squash per 8-group, store
#pragma unroll
    for (int j = 0; j < 2; j++)
#pragma unroll
        for (int q = 0; q < 4; q++)
#pragma unroll
            for (int h = 0; h < 2; h++) {
                float lo, hi;
                UNPACK2(lo, hi, acc2[j][q * 2 + h]);
                int oc = og * 4 + q * 64 + h * 2;
                wsh[lg * 2 + j][oc]     = lo + b1s[oc];
                wsh[lg * 2 + j][oc + 1] = hi + b1s[oc + 1];
            }
    __syncthreads();
#pragma unroll
    for (int g = t; g < 512; g += 128) {
        int l_loc = g >> 5, cp = g & 31;
        float4 a = *(const float4*)&wsh[l_loc][cp * 8];
        float4 c = *(const float4*)&wsh[l_loc][cp * 8 + 4];
        float sq = (a.x * a.x + a.y * a.y) + (a.z * a.z + a.w * a.w)
                 + (c.x * c.x + c.y * c.y) + (c.z * c.z + c.w * c.w);
        float scale = sq / (1.f + sq) * rsqrtf(sq + 1e-8f);
        a.x *= scale; a.y *= scale; a.z *= scale; a.w *= scale;
        c.x *= scale; c.y *= scale; c.z *= scale; c.w *= scale;
        int l = l0 + l_loc;
        float* dst = &g_yq[((size_t)(b * L_ + l)) * NOC1 + cp * 8];
        *(float4*)dst       = a;
        *(float4*)(dst + 4) = c;
    }
}

// ---------------------------------------------------------------------------
// Kernel 2: conv2 + 3-iter routing. LATENCY-ORIENTED: every reduction uses
// multiple independent accumulator chains (V-compute 2, s-loop 4, dots 2).
// ---------------------------------------------------------------------------
__global__ __launch_bounds__(256) void conv2_route_kernel(
    const float* __restrict__ w2, const float* __restrict__ b2,
    float* __restrict__ out)
{
    __shared__ float yq3[3][NOC1];          // rows l-1, l, l+1
    __shared__ float ef[CP_][17];           // exp(logits), padded
    __shared__ float sinv[CP_];             // 1/rowsum
    __shared__ float vsh[16][16];           // v values [csa][asa]
    __shared__ float Vs[16][16][VPAD];      // V mirror [csa][asa][cp]

    const int bl = blockIdx.x;
    const int l  = bl & (L_ - 1);
    const int t  = threadIdx.x;

    {
        const float* base = g_yq + (size_t)bl * NOC1;
        yq3[1][t] = base[t];
        yq3[0][t] = (l > 0)      ? base[t - NOC1] : 0.f;
        yq3[2][t] = (l < L_ - 1) ? base[t + NOC1] : 0.f;
    }

    ull w2p[12];
    {
        const float2* wrow = (const float2*)(w2 + t * 24);
#pragma unroll
        for (int h = 0; h < 12; h++) {
            float2 wv = wrow[h];
            asm("mov.b64 %0, {%1, %2};" : "=l"(w2p[h]) : "f"(wv.x), "f"(wv.y));
        }
    }
    const float bias = b2[t];
    __syncthreads();

    // V[cp]: TWO independent FFMA2 chains per cp (6 deep each)
    float V[CP_];
#pragma unroll
    for (int cp = 0; cp < CP_; cp++) {
        ull accA, accB;
        asm("mov.b64 %0, {%1, %2};" : "=l"(accA) : "f"(bias), "f"(0.f));
        accB = 0ULL;
        const ulonglong2* y0 = (const ulonglong2*)&yq3[0][cp * 8];
        const ulonglong2* y1 = (const ulonglong2*)&yq3[1][cp * 8];
        const ulonglong2* y2 = (const ulonglong2*)&yq3[2][cp * 8];
        ulonglong2 a0 = y0[0], b0v = y0[1];
        ulonglong2 a1 = y1[0], b1v = y1[1];
        ulonglong2 a2 = y2[0], b2v = y2[1];
        FFMA2(accA, a0.x, w2p[0]);
        FFMA2(accB, a0.y, w2p[1]);
        FFMA2(accA, b0v.x, w2p[2]);
        FFMA2(accB, b0v.y, w2p[3]);
        FFMA2(accA, a1.x, w2p[4]);
        FFMA2(accB, a1.y, w2p[5]);
        FFMA2(accA, b1v.x, w2p[6]);
        FFMA2(accB, b1v.y, w2p[7]);
        FFMA2(accA, a2.x, w2p[8]);
        FFMA2(accB, a2.y, w2p[9]);
        FFMA2(accA, b2v.x, w2p[10]);
        FFMA2(accB, b2v.y, w2p[11]);
        float loA, hiA, loB, hiB;
        UNPACK2(loA, hiA, accA);
        UNPACK2(loB, hiB, accB);
        V[cp] = (loA + hiA) + (loB + hiB);
    }

    const int csa = t >> 4;
    const int asa = t & 15;

    // Mirror V to smem for the a-update phase
#pragma unroll
    for (int q = 0; q < 8; q++) {
        float4 vv = make_float4(V[q * 4], V[q * 4 + 1], V[q * 4 + 2], V[q * 4 + 3]);
        *(float4*)&Vs[csa][asa][q * 4] = vv;
    }

    // ---- r = 0: uniform softmax (4 partial sums) ----
    float v;
    {
        float s0 = 0.f, s1 = 0.f, s2 = 0.f, s3 = 0.f;
#pragma unroll
        for (int cp = 0; cp < CP_; cp += 4) {
            s0 += V[cp]; s1 += V[cp + 1]; s2 += V[cp + 2]; s3 += V[cp + 3];
        }
        float s = ((s0 + s1) + (s2 + s3)) * (1.f / 16.f);
        float sq = s * s;
        sq += __shfl_xor_sync(0xffffffffu, sq, 1);
        sq += __shfl_xor_sync(0xffffffffu, sq, 2);
        sq += __shfl_xor_sync(0xffffffffu, sq, 4);
        sq += __shfl_xor_sync(0xffffffffu, sq, 8);
        float scale = sq / (1.f + sq) * rsqrtf(sq + 1e-8f);
        v = s * scale;
    }
    vsh[csa][asa] = v;
    __syncthreads();

    // a-update mapping: thread owns pairs (cp_a, cs0) and (cp_a, cs0+8)
    const int cp_a = t & 31;
    const int cs0  = t >> 5;       // 0..7
    float blog0, blog1;
    {
        const float4* vpA = (const float4*)vsh[cs0];
        const float4* vpB = (const float4*)vsh[cs0 + 8];
        float4 vA0 = vpA[0], vA1 = vpA[1], vA2 = vpA[2], vA3 = vpA[3];
        float4 vB0 = vpB[0], vB1 = vpB[1], vB2 = vpB[2], vB3 = vpB[3];
        const float* VsA = &Vs[cs0][0][cp_a];
        const float* VsB = &Vs[cs0 + 8][0][cp_a];
        float p0, p1, q0, q1;
        p0  = VsA[0*VPAD]*vA0.x + VsA[1*VPAD]*vA0.y + VsA[2*VPAD]*vA0.z + VsA[3*VPAD]*vA0.w;
        p1  = VsA[4*VPAD]*vA1.x + VsA[5*VPAD]*vA1.y + VsA[6*VPAD]*vA1.z + VsA[7*VPAD]*vA1.w;
        p0 += VsA[8*VPAD]*vA2.x + VsA[9*VPAD]*vA2.y + VsA[10*VPAD]*vA2.z + VsA[11*VPAD]*vA2.w;
        p1 += VsA[12*VPAD]*vA3.x + VsA[13*VPAD]*vA3.y + VsA[14*VPAD]*vA3.z + VsA[15*VPAD]*vA3.w;
        q0  = VsB[0*VPAD]*vB0.x + VsB[1*VPAD]*vB0.y + VsB[2*VPAD]*vB0.z + VsB[3*VPAD]*vB0.w;
        q1  = VsB[4*VPAD]*vB1.x + VsB[5*VPAD]*vB1.y + VsB[6*VPAD]*vB1.z + VsB[7*VPAD]*vB1.w;
        q0 += VsB[8*VPAD]*vB2.x + VsB[9*VPAD]*vB2.y + VsB[10*VPAD]*vB2.z + VsB[11*VPAD]*vB2.w;
        q1 += VsB[12*VPAD]*vB3.x + VsB[13*VPAD]*vB3.y + VsB[14*VPAD]*vB3.z + VsB[15*VPAD]*vB3.w;
        blog0 = p0 + p1;
        blog1 = q0 + q1;
    }

    // ---- r = 1, 2 ----
#pragma unroll
    for (int r = 1; r < 3; r++) {
        ef[cp_a][cs0]     = __expf(blog0);
        ef[cp_a][cs0 + 8] = __expf(blog1);
        __syncthreads();
        if (t < CP_) {
            const float* er = ef[t];
            float u0 = 0.f, u1 = 0.f, u2 = 0.f, u3 = 0.f;
#pragma unroll
            for (int j2 = 0; j2 < CSA_; j2 += 4) {
                u0 += er[j2]; u1 += er[j2 + 1]; u2 += er[j2 + 2]; u3 += er[j2 + 3];
            }
            sinv[t] = __fdividef(1.f, (u0 + u1) + (u2 + u3));
        }
        __syncthreads();

        // s = sum_cp ef[cp][csa] * sinv[cp] * V[cp]  (4 partial chains)
        float s0 = 0.f, s1 = 0.f, s2 = 0.f, s3 = 0.f;
#pragma unroll
        for (int cp = 0; cp < CP_; cp += 4) {
            s0 += ef[cp][csa]     * (sinv[cp]     * V[cp]);
            s1 += ef[cp + 1][csa] * (sinv[cp + 1] * V[cp + 1]);
            s2 += ef[cp + 2][csa] * (sinv[cp + 2] * V[cp + 2]);
            s3 += ef[cp + 3][csa] * (sinv[cp + 3] * V[cp + 3]);
        }
        float s = (s0 + s1) + (s2 + s3);

        float sq = s * s;
        sq += __shfl_xor_sync(0xffffffffu, sq, 1);
        sq += __shfl_xor_sync(0xffffffffu, sq, 2);
        sq += __shfl_xor_sync(0xffffffffu, sq, 4);
        sq += __shfl_xor_sync(0xffffffffu, sq, 8);
        float scale = sq / (1.f + sq) * rsqrtf(sq + 1e-8f);
        v = s * scale;

        if (r < 2) {
            vsh[csa][asa] = v;
            __syncthreads();
            const float4* vpA = (const float4*)vsh[cs0];
            const float4* vpB = (const float4*)vsh[cs0 + 8];
            float4 vA0 = vpA[0], vA1 = vpA[1], vA2 = vpA[2], vA3 = vpA[3];
            float4 vB0 = vpB[0], vB1 = vpB[1], vB2 = vpB[2], vB3 = vpB[3];
            const float* VsA = &Vs[cs0][0][cp_a];
            const float* VsB = &Vs[cs0 + 8][0][cp_a];
            float p0, p1, q0, q1;
            p0  = VsA[0*VPAD]*vA0.x + VsA[1*VPAD]*vA0.y + VsA[2*VPAD]*vA0.z + VsA[3*VPAD]*vA0.w;
            p1  = VsA[4*VPAD]*vA1.x + VsA[5*VPAD]*vA1.y + VsA[6*VPAD]*vA1.z + VsA[7*VPAD]*vA1.w;
            p0 += VsA[8*VPAD]*vA2.x + VsA[9*VPAD]*vA2.y + VsA[10*VPAD]*vA2.z + VsA[11*VPAD]*vA2.w;
            p1 += VsA[12*VPAD]*vA3.x + VsA[13*VPAD]*vA3.y + VsA[14*VPAD]*vA3.z + VsA[15*VPAD]*vA3.w;
            q0  = VsB[0*VPAD]*vB0.x + VsB[1*VPAD]*vB0.y + VsB[2*VPAD]*vB0.z + VsB[3*VPAD]*vB0.w;
            q1  = VsB[4*VPAD]*vB1.x + VsB[5*VPAD]*vB1.y + VsB[6*VPAD]*vB1.z + VsB[7*VPAD]*vB1.w;
            q0 += VsB[8*VPAD]*vB2.x + VsB[9*VPAD]*vB2.y + VsB[10*VPAD]*vB2.z + VsB[11*VPAD]*vB2.w;
            q1 += VsB[12*VPAD]*vB3.x + VsB[13*VPAD]*vB3.y + VsB[14*VPAD]*vB3.z + VsB[15*VPAD]*vB3.w;
            blog0 += p0 + p1;
            blog1 += q0 + q1;
        }
    }

    out[(size_t)bl * 256 + t] = v;
}

// ---------------------------------------------------------------------------
extern "C" void kernel_launch(void* const* d_in, const int* in_sizes, int n_in,
                              void* d_out, int out_size)
{
    const float* x  = (const float*)d_in[0];   // [8, 64, 1024]
    const float* w1 = (const float*)d_in[1];   // [256, 64, 9]
    const float* b1 = (const float*)d_in[2];   // [256]
    const float* w2 = (const float*)d_in[3];   // [256, 1, 3, 8]
    const float* b2 = (const float*)d_in[4];   // [256]
    float* out = (float*)d_out;                // [8, 16384, 16]

    prep_kernel<<<576, 256>>>(w1);
    conv1_squash_kernel<<<dim3(L_ / 16, B_), 128>>>(x, b1);
    conv2_route_kernel<<<B_ * L_, 256>>>(w2, b2, out);
}

// round 11
// speedup vs baseline: 1.1375x; 1.0312x over previous
#include <cuda_runtime.h>

// Problem constants
#define B_    8
#define K_    64
#define L_    1024
#define CP_   32
#define CSA_  16
#define NOC1  256
#define K1    576          // K_*G2_
#define VPAD  36           // Vs cp-dim pad
#define EPAD  36           // efT cp-dim pad (16B-aligned rows, 2-way worst)

typedef unsigned long long ull;

// Packed fp32x2 helpers (sm_100+)
#define FFMA2(acc, a, b) asm("fma.rn.f32x2 %0, %1, %2, %0;" : "+l"(acc) : "l"(a), "l"(b))
#define MUL2(dst, a, b)  asm("mul.rn.f32x2 %0, %1, %2;" : "=l"(dst) : "l"(a), "l"(b))
#define ADD2(dst, a, b)  asm("add.rn.f32x2 %0, %1, %2;" : "=l"(dst) : "l"(a), "l"(b))
#define PACK2(dst, f)    asm("mov.b64 %0, {%1, %1};" : "=l"(dst) : "f"(f))
#define PACKAB(dst, a, b) asm("mov.b64 %0, {%1, %2};" : "=l"(dst) : "f"(a), "f"(b))
#define UNPACK2(lo, hi, v) asm("mov.b64 {%0, %1}, %2;" : "=f"(lo), "=f"(hi) : "l"(v))

// Scratch (allocation-free: device globals)
__device__ float g_yq[B_ * L_ * NOC1];      // squashed conv1 output [B, L, 256]
__device__ float g_wT[K1 * NOC1];           // conv1 weights transposed [k][oc]

// ---------------------------------------------------------------------------
// Prep: transpose conv1 weights for coalesced streaming
// ---------------------------------------------------------------------------
__global__ void prep_kernel(const float* __restrict__ w1) {
    int idx = blockIdx.x * 256 + threadIdx.x;
    if (idx < K1 * NOC1) {
        int k = idx >> 8, oc = idx & 255;
        g_wT[idx] = w1[oc * K1 + k];
    }
}

// ---------------------------------------------------------------------------
// Kernel 1: conv1 (implicit GEMM, 'SAME') + bias + squash. (R10-exact)
// ---------------------------------------------------------------------------
__global__ __launch_bounds__(128) void conv1_squash_kernel(
    const float* __restrict__ x, const float* __restrict__ b1)
{
    __shared__ float xs[K_][24];
    __shared__ float wsh[16][NOC1];
    __shared__ float b1s[NOC1];

    const int b  = blockIdx.y;
    const int l0 = blockIdx.x * 16;
    const int t  = threadIdx.x;

    b1s[t]       = b1[t];
    b1s[t + 128] = b1[t + 128];
    for (int i = t; i < K_ * 24; i += 128) {
        int ic = i / 24, jj = i - ic * 24;
        int l = l0 - 4 + jj;
        xs[ic][jj] = (l >= 0 && l < L_) ? x[(b * K_ + ic) * L_ + l] : 0.f;
    }

    ull acc2[2][8];
#pragma unroll
    for (int j = 0; j < 2; j++)
#pragma unroll
        for (int i = 0; i < 8; i++) acc2[j][i] = 0ULL;

    const int lg = t >> 4;
    const int og = t & 15;
    __syncthreads();

    const float4* wT4 = (const float4*)g_wT;
    for (int kc = 0; kc < K1; kc += 16) {
#pragma unroll
        for (int i = 0; i < 8; i++)
            ((float4*)wsh)[t + i * 128] = wT4[kc * 64 + t + i * 128];
        __syncthreads();
#pragma unroll
        for (int kk = 0; kk < 16; kk++) {
            int k  = kc + kk;
            int ic = k / 9;
            int tt = k - ic * 9;
            float xv0 = xs[ic][lg * 2 + tt];
            float xv1 = xs[ic][lg * 2 + 1 + tt];
            ull X0, X1;
            PACK2(X0, xv0);
            PACK2(X1, xv1);
#pragma unroll
            for (int q = 0; q < 4; q++) {
                ulonglong2 wq = *(const ulonglong2*)&wsh[kk][og * 4 + q * 64];
                FFMA2(acc2[0][q * 2 + 0], X0, wq.x);
                FFMA2(acc2[0][q * 2 + 1], X0, wq.y);
                FFMA2(acc2[1][q * 2 + 0], X1, wq.x);
                FFMA2(acc2[1][q * 2 + 1], X1, wq.y);
            }
        }
        __syncthreads();
    }

#pragma unroll
    for (int j = 0; j < 2; j++)
#pragma unroll
        for (int q = 0; q < 4; q++)
#pragma unroll
            for (int h = 0; h < 2; h++) {
                float lo, hi;
                UNPACK2(lo, hi, acc2[j][q * 2 + h]);
                int oc = og * 4 + q * 64 + h * 2;
                wsh[lg * 2 + j][oc]     = lo + b1s[oc];
                wsh[lg * 2 + j][oc + 1] = hi + b1s[oc + 1];
            }
    __syncthreads();
#pragma unroll
    for (int g = t; g < 512; g += 128) {
        int l_loc = g >> 5, cp = g & 31;
        float4 a = *(const float4*)&wsh[l_loc][cp * 8];
        float4 c = *(const float4*)&wsh[l_loc][cp * 8 + 4];
        float sq = (a.x * a.x + a.y * a.y) + (a.z * a.z + a.w * a.w)
                 + (c.x * c.x + c.y * c.y) + (c.z * c.z + c.w * c.w);
        float scale = sq / (1.f + sq) * rsqrtf(sq + 1e-8f);
        a.x *= scale; a.y *= scale; a.z *= scale; a.w *= scale;
        c.x *= scale; c.y *= scale; c.z *= scale; c.w *= scale;
        int l = l0 + l_loc;
        float* dst = &g_yq[((size_t)(b * L_ + l)) * NOC1 + cp * 8];
        *(float4*)dst       = a;
        *(float4*)(dst + 4) = c;
    }
}

// ---------------------------------------------------------------------------
// Kernel 2: conv2 + 3-iter routing. PACKED: V kept as 16 f32x2 pairs; softmax
// coefficients stored transposed (efT) so the s-reduction is packed LDS.128 +
// MUL2/FFMA2. a-update reads scalar Vs (bytes identical to packed stores).
// ---------------------------------------------------------------------------
__global__ __launch_bounds__(256) void conv2_route_kernel(
    const float* __restrict__ w2, const float* __restrict__ b2,
    float* __restrict__ out)
{
    __shared__ float yq3[3][NOC1];              // rows l-1, l, l+1
    __shared__ float efT[CSA_][EPAD];           // exp(logits) transposed [csa][cp]
    __shared__ __align__(16) float sinv[CP_];   // 1/rowsum (LDS.128 pairs)
    __shared__ float vsh[16][16];               // v values [csa][asa]
    __shared__ float Vs[16][16][VPAD];          // V mirror [csa][asa][cp]

    const int bl = blockIdx.x;
    const int l  = bl & (L_ - 1);
    const int t  = threadIdx.x;

    {
        const float* base = g_yq + (size_t)bl * NOC1;
        yq3[1][t] = base[t];
        yq3[0][t] = (l > 0)      ? base[t - NOC1] : 0.f;
        yq3[2][t] = (l < L_ - 1) ? base[t + NOC1] : 0.f;
    }

    ull w2p[12];
    {
        const float2* wrow = (const float2*)(w2 + t * 24);
#pragma unroll
        for (int h = 0; h < 12; h++) {
            float2 wv = wrow[h];
            PACKAB(w2p[h], wv.x, wv.y);
        }
    }
    const float bias = b2[t];
    __syncthreads();

    const int csa = t >> 4;
    const int asa = t & 15;

    // V as packed pairs V2[m] = {V[2m], V[2m+1]}; two interleaved FFMA2 chains
    ull V2[16];
#pragma unroll
    for (int m = 0; m < 16; m++) {
        ull accA, accB;
        PACKAB(accA, bias, 0.f);
        PACKAB(accB, bias, 0.f);
        const int cA = 2 * m, cB = 2 * m + 1;
        const ulonglong2* a0p = (const ulonglong2*)&yq3[0][cA * 8];
        const ulonglong2* a1p = (const ulonglong2*)&yq3[1][cA * 8];
        const ulonglong2* a2p = (const ulonglong2*)&yq3[2][cA * 8];
        const ulonglong2* b0p = (const ulonglong2*)&yq3[0][cB * 8];
        const ulonglong2* b1p = (const ulonglong2*)&yq3[1][cB * 8];
        const ulonglong2* b2p = (const ulonglong2*)&yq3[2][cB * 8];
        ulonglong2 a0 = a0p[0], a0b = a0p[1];
        ulonglong2 c0 = b0p[0], c0b = b0p[1];
        FFMA2(accA, a0.x, w2p[0]);  FFMA2(accB, c0.x, w2p[0]);
        FFMA2(accA, a0.y, w2p[1]);  FFMA2(accB, c0.y, w2p[1]);
        FFMA2(accA, a0b.x, w2p[2]); FFMA2(accB, c0b.x, w2p[2]);
        FFMA2(accA, a0b.y, w2p[3]); FFMA2(accB, c0b.y, w2p[3]);
        ulonglong2 a1 = a1p[0], a1b = a1p[1];
        ulonglong2 c1 = b1p[0], c1b = b1p[1];
        FFMA2(accA, a1.x, w2p[4]);  FFMA2(accB, c1.x, w2p[4]);
        FFMA2(accA, a1.y, w2p[5]);  FFMA2(accB, c1.y, w2p[5]);
        FFMA2(accA, a1b.x, w2p[6]); FFMA2(accB, c1b.x, w2p[6]);
        FFMA2(accA, a1b.y, w2p[7]); FFMA2(accB, c1b.y, w2p[7]);
        ulonglong2 a2 = a2p[0], a2b = a2p[1];
        ulonglong2 c2 = b2p[0], c2b = b2p[1];
        FFMA2(accA, a2.x, w2p[8]);  FFMA2(accB, c2.x, w2p[8]);
        FFMA2(accA, a2.y, w2p[9]);  FFMA2(accB, c2.y, w2p[9]);
        FFMA2(accA, a2b.x, w2p[10]); FFMA2(accB, c2b.x, w2p[10]);
        FFMA2(accA, a2b.y, w2p[11]); FFMA2(accB, c2b.y, w2p[11]);
        float lA, hA, lB, hB;
        UNPACK2(lA, hA, accA);
        UNPACK2(lB, hB, accB);
        PACKAB(V2[m], lA + hA, lB + hB);
    }

    // Mirror V to smem (bytes of V2 pairs == scalar layout)
#pragma unroll
    for (int m = 0; m < 16; m++)
        *(ull*)&Vs[csa][asa][2 * m] = V2[m];

    // ---- r = 0: uniform softmax (packed sum, 4 chains) ----
    float v;
    {
        ull t0 = V2[0], t1 = V2[1], t2 = V2[2], t3 = V2[3];
#pragma unroll
        for (int m = 4; m < 16; m += 4) {
            ADD2(t0, t0, V2[m]);
            ADD2(t1, t1, V2[m + 1]);
            ADD2(t2, t2, V2[m + 2]);
            ADD2(t3, t3, V2[m + 3]);
        }
        ADD2(t0, t0, t1);
        ADD2(t2, t2, t3);
        ADD2(t0, t0, t2);
        float lo, hi;
        UNPACK2(lo, hi, t0);
        float s = (lo + hi) * (1.f / 16.f);
        float sq = s * s;
        sq += __shfl_xor_sync(0xffffffffu, sq, 1);
        sq += __shfl_xor_sync(0xffffffffu, sq, 2);
        sq += __shfl_xor_sync(0xffffffffu, sq, 4);
        sq += __shfl_xor_sync(0xffffffffu, sq, 8);
        float scale = sq / (1.f + sq) * rsqrtf(sq + 1e-8f);
        v = s * scale;
    }
    vsh[csa][asa] = v;
    __syncthreads();

    // a-update mapping: thread owns pairs (cp_a, cs0) and (cp_a, cs0+8)
    const int cp_a = t & 31;
    const int cs0  = t >> 5;
    float blog0, blog1;
    {
        const float4* vpA = (const float4*)vsh[cs0];
        const float4* vpB = (const float4*)vsh[cs0 + 8];
        float4 vA0 = vpA[0], vA1 = vpA[1], vA2 = vpA[2], vA3 = vpA[3];
        float4 vB0 = vpB[0], vB1 = vpB[1], vB2 = vpB[2], vB3 = vpB[3];
        const float* VsA = &Vs[cs0][0][cp_a];
        const float* VsB = &Vs[cs0 + 8][0][cp_a];
        float p0, p1, q0, q1;
        p0  = VsA[0*VPAD]*vA0.x + VsA[1*VPAD]*vA0.y + VsA[2*VPAD]*vA0.z + VsA[3*VPAD]*vA0.w;
        p1  = VsA[4*VPAD]*vA1.x + VsA[5*VPAD]*vA1.y + VsA[6*VPAD]*vA1.z + VsA[7*VPAD]*vA1.w;
        p0 += VsA[8*VPAD]*vA2.x + VsA[9*VPAD]*vA2.y + VsA[10*VPAD]*vA2.z + VsA[11*VPAD]*vA2.w;
        p1 += VsA[12*VPAD]*vA3.x + VsA[13*VPAD]*vA3.y + VsA[14*VPAD]*vA3.z + VsA[15*VPAD]*vA3.w;
        q0  = VsB[0*VPAD]*vB0.x + VsB[1*VPAD]*vB0.y + VsB[2*VPAD]*vB0.z + VsB[3*VPAD]*vB0.w;
        q1  = VsB[4*VPAD]*vB1.x + VsB[5*VPAD]*vB1.y + VsB[6*VPAD]*vB1.z + VsB[7*VPAD]*vB1.w;
        q0 += VsB[8*VPAD]*vB2.x + VsB[9*VPAD]*vB2.y + VsB[10*VPAD]*vB2.z + VsB[11*VPAD]*vB2.w;
        q1 += VsB[12*VPAD]*vB3.x + VsB[13*VPAD]*vB3.y + VsB[14*VPAD]*vB3.z + VsB[15*VPAD]*vB3.w;
        blog0 = p0 + p1;
        blog1 = q0 + q1;
    }

    // ---- r = 1, 2 ----
#pragma unroll
    for (int r = 1; r < 3; r++) {
        efT[cs0][cp_a]     = __expf(blog0);
        efT[cs0 + 8][cp_a] = __expf(blog1);
        __syncthreads();
        if (t < CP_) {
            float u0 = 0.f, u1 = 0.f, u2 = 0.f, u3 = 0.f;
#pragma unroll
            for (int j2 = 0; j2 < CSA_; j2 += 4) {
                u0 += efT[j2][t];     u1 += efT[j2 + 1][t];
                u2 += efT[j2 + 2][t]; u3 += efT[j2 + 3][t];
            }
            sinv[t] = __fdividef(1.f, (u0 + u1) + (u2 + u3));
        }
        __syncthreads();

        // packed s = sum_cp efT[csa][cp]*sinv[cp]*V[cp]
        ull s2a = 0ULL, s2b = 0ULL, s2c = 0ULL, s2d = 0ULL;
        const ulonglong2* efp = (const ulonglong2*)&efT[csa][0];
        const ulonglong2* svp = (const ulonglong2*)sinv;
#pragma unroll
        for (int q = 0; q < 8; q++) {
            ulonglong2 e2 = efp[q];
            ulonglong2 n2 = svp[q];
            ull p0, p1;
            MUL2(p0, e2.x, n2.x);
            MUL2(p1, e2.y, n2.y);
            if (q & 1) {
                FFMA2(s2c, p0, V2[2 * q]);
                FFMA2(s2d, p1, V2[2 * q + 1]);
            } else {
                FFMA2(s2a, p0, V2[2 * q]);
                FFMA2(s2b, p1, V2[2 * q + 1]);
            }
        }
        ADD2(s2a, s2a, s2b);
        ADD2(s2c, s2c, s2d);
        ADD2(s2a, s2a, s2c);
        float lo, hi;
        UNPACK2(lo, hi, s2a);
        float s = lo + hi;

        float sq = s * s;
        sq += __shfl_xor_sync(0xffffffffu, sq, 1);
        sq += __shfl_xor_sync(0xffffffffu, sq, 2);
        sq += __shfl_xor_sync(0xffffffffu, sq, 4);
        sq += __shfl_xor_sync(0xffffffffu, sq, 8);
        float scale = sq / (1.f + sq) * rsqrtf(sq + 1e-8f);
        v = s * scale;

        if (r < 2) {
            vsh[csa][asa] = v;
            __syncthreads();
            const float4* vpA = (const float4*)vsh[cs0];
            const float4* vpB = (const float4*)vsh[cs0 + 8];
            float4 vA0 = vpA[0], vA1 = vpA[1], vA2 = vpA[2], vA3 = vpA[3];
            float4 vB0 = vpB[0], vB1 = vpB[1], vB2 = vpB[2], vB3 = vpB[3];
            const float* VsA = &Vs[cs0][0][cp_a];
            const float* VsB = &Vs[cs0 + 8][0][cp_a];
            float p0, p1, q0, q1;
            p0  = VsA[0*VPAD]*vA0.x + VsA[1*VPAD]*vA0.y + VsA[2*VPAD]*vA0.z + VsA[3*VPAD]*vA0.w;
            p1  = VsA[4*VPAD]*vA1.x + VsA[5*VPAD]*vA1.y + VsA[6*VPAD]*vA1.z + VsA[7*VPAD]*vA1.w;
            p0 += VsA[8*VPAD]*vA2.x + VsA[9*VPAD]*vA2.y + VsA[10*VPAD]*vA2.z + VsA[11*VPAD]*vA2.w;
            p1 += VsA[12*VPAD]*vA3.x + VsA[13*VPAD]*vA3.y + VsA[14*VPAD]*vA3.z + VsA[15*VPAD]*vA3.w;
            q0  = VsB[0*VPAD]*vB0.x + VsB[1*VPAD]*vB0.y + VsB[2*VPAD]*vB0.z + VsB[3*VPAD]*vB0.w;
            q1  = VsB[4*VPAD]*vB1.x + VsB[5*VPAD]*vB1.y + VsB[6*VPAD]*vB1.z + VsB[7*VPAD]*vB1.w;
            q0 += VsB[8*VPAD]*vB2.x + VsB[9*VPAD]*vB2.y + VsB[10*VPAD]*vB2.z + VsB[11*VPAD]*vB2.w;
            q1 += VsB[12*VPAD]*vB3.x + VsB[13*VPAD]*vB3.y + VsB[14*VPAD]*vB3.z + VsB[15*VPAD]*vB3.w;
            blog0 += p0 + p1;
            blog1 += q0 + q1;
        }
    }

    out[(size_t)bl * 256 + t] = v;
}

// ---------------------------------------------------------------------------
extern "C" void kernel_launch(void* const* d_in, const int* in_sizes, int n_in,
                              void* d_out, int out_size)
{
    const float* x  = (const float*)d_in[0];   // [8, 64, 1024]
    const float* w1 = (const float*)d_in[1];   // [256, 64, 9]
    const float* b1 = (const float*)d_in[2];   // [256]
    const float* w2 = (const float*)d_in[3];   // [256, 1, 3, 8]
    const float* b2 = (const float*)d_in[4];   // [256]
    float* out = (float*)d_out;                // [8, 16384, 16]

    prep_kernel<<<576, 256>>>(w1);
    conv1_squash_kernel<<<dim3(L_ / 16, B_), 128>>>(x, b1);
    conv2_route_kernel<<<B_ * L_, 256>>>(w2, b2, out);
}

// round 12
// speedup vs baseline: 1.2656x; 1.1127x over previous
#include <cuda_runtime.h>

// Problem constants
#define B_    8
#define K_    64
#define L_    1024
#define CP_   32
#define CSA_  16
#define NOC1  256
#define K1    576          // K_*G2_
#define VPAD  36           // Vs cp-dim pad (16B-aligned rows)
#define EPAD  36           // efT cp-dim pad
#define YPAD  28           // yph/ypl k-dim pad (conflict-free b-frags)

typedef unsigned long long ull;

// Packed fp32x2 helpers (sm_100+)
#define FFMA2(acc, a, b) asm("fma.rn.f32x2 %0, %1, %2, %0;" : "+l"(acc) : "l"(a), "l"(b))
#define MUL2(dst, a, b)  asm("mul.rn.f32x2 %0, %1, %2;" : "=l"(dst) : "l"(a), "l"(b))
#define ADD2(dst, a, b)  asm("add.rn.f32x2 %0, %1, %2;" : "=l"(dst) : "l"(a), "l"(b))
#define PACK2(dst, f)    asm("mov.b64 %0, {%1, %1};" : "=l"(dst) : "f"(f))
#define UNPACK2(lo, hi, v) asm("mov.b64 {%0, %1}, %2;" : "=f"(lo), "=f"(hi) : "l"(v))

// tf32 mma: D(16x8) += A(16x8,row) * B(8x8,col)
#define MMA_TF32(c, au, b0, b1) \
    asm("mma.sync.aligned.m16n8k8.row.col.f32.tf32.tf32.f32 " \
        "{%0,%1,%2,%3},{%4,%5,%6,%7},{%8,%9},{%0,%1,%2,%3};" \
        : "+f"((c)[0]), "+f"((c)[1]), "+f"((c)[2]), "+f"((c)[3]) \
        : "r"((au).x), "r"((au).y), "r"((au).z), "r"((au).w), "r"(b0), "r"(b1))

__device__ __forceinline__ float t32hi(float x) {
    return __uint_as_float(__float_as_uint(x) & 0xFFFFE000u);
}

// Scratch (allocation-free: device globals)
__device__ float g_yq[B_ * L_ * NOC1];      // squashed conv1 output
__device__ float g_wT[K1 * NOC1];           // conv1 weights transposed [k][oc]
__device__ float g_w2f[2 * 16 * 3 * 128];   // conv2 w fragments [split][mt][k][lane*4+i]

// ---------------------------------------------------------------------------
// Prep: conv1 weight transpose + conv2 weight fragment (hi/lo split) build
// ---------------------------------------------------------------------------
__global__ void prep_kernel(const float* __restrict__ w1, const float* __restrict__ w2) {
    int idx = blockIdx.x * 256 + threadIdx.x;
    if (idx < K1 * NOC1) {
        int k = idx >> 8, oc = idx & 255;
        g_wT[idx] = w1[oc * K1 + k];
    }
    if (idx < 2 * 16 * 3 * 128) {
        int i    = idx & 3;
        int lane = (idx >> 2) & 31;
        int rest = idx >> 7;            // split*48 + mt*3 + k
        int k    = rest % 3;
        int mt   = (rest / 3) & 15;
        int split = rest / 48;
        int group = lane >> 2, tid = lane & 3;
        int row = ((i & 1) << 3) + group;       // a0:(g),a1:(g+8),a2:(g),a3:(g+8)
        int col = ((i >> 1) << 2) + tid;        // a0,a1: tid ; a2,a3: tid+4
        float val = w2[(mt * 16 + row) * 24 + k * 8 + col];
        float hi = t32hi(val);
        g_w2f[idx] = split ? (val - hi) : hi;
    }
}

// ---------------------------------------------------------------------------
// Kernel 1: conv1 (implicit GEMM, 'SAME') + bias + squash. (best-measured)
// ---------------------------------------------------------------------------
__global__ __launch_bounds__(128) void conv1_squash_kernel(
    const float* __restrict__ x, const float* __restrict__ b1)
{
    __shared__ float xs[K_][24];
    __shared__ float wsh[16][NOC1];
    __shared__ float b1s[NOC1];

    const int b  = blockIdx.y;
    const int l0 = blockIdx.x * 16;
    const int t  = threadIdx.x;

    b1s[t]       = b1[t];
    b1s[t + 128] = b1[t + 128];
    for (int i = t; i < K_ * 24; i += 128) {
        int ic = i / 24, jj = i - ic * 24;
        int l = l0 - 4 + jj;
        xs[ic][jj] = (l >= 0 && l < L_) ? x[(b * K_ + ic) * L_ + l] : 0.f;
    }

    ull acc2[2][8];
#pragma unroll
    for (int j = 0; j < 2; j++)
#pragma unroll
        for (int i = 0; i < 8; i++) acc2[j][i] = 0ULL;

    const int lg = t >> 4;
    const int og = t & 15;
    __syncthreads();

    const float4* wT4 = (const float4*)g_wT;
    for (int kc = 0; kc < K1; kc += 16) {
#pragma unroll
        for (int i = 0; i < 8; i++)
            ((float4*)wsh)[t + i * 128] = wT4[kc * 64 + t + i * 128];
        __syncthreads();
#pragma unroll
        for (int kk = 0; kk < 16; kk++) {
            int k  = kc + kk;
            int ic = k / 9;
            int tt = k - ic * 9;
            float xv0 = xs[ic][lg * 2 + tt];
            float xv1 = xs[ic][lg * 2 + 1 + tt];
            ull X0, X1;
            PACK2(X0, xv0);
            PACK2(X1, xv1);
#pragma unroll
            for (int q = 0; q < 4; q++) {
                ulonglong2 wq = *(const ulonglong2*)&wsh[kk][og * 4 + q * 64];
                FFMA2(acc2[0][q * 2 + 0], X0, wq.x);
                FFMA2(acc2[0][q * 2 + 1], X0, wq.y);
                FFMA2(acc2[1][q * 2 + 0], X1, wq.x);
                FFMA2(acc2[1][q * 2 + 1], X1, wq.y);
            }
        }
        __syncthreads();
    }

#pragma unroll
    for (int j = 0; j < 2; j++)
#pragma unroll
        for (int q = 0; q < 4; q++)
#pragma unroll
            for (int h = 0; h < 2; h++) {
                float lo, hi;
                UNPACK2(lo, hi, acc2[j][q * 2 + h]);
                int oc = og * 4 + q * 64 + h * 2;
                wsh[lg * 2 + j][oc]     = lo + b1s[oc];
                wsh[lg * 2 + j][oc + 1] = hi + b1s[oc + 1];
            }
    __syncthreads();
#pragma unroll
    for (int g = t; g < 512; g += 128) {
        int l_loc = g >> 5, cp = g & 31;
        float4 a = *(const float4*)&wsh[l_loc][cp * 8];
        float4 c = *(const float4*)&wsh[l_loc][cp * 8 + 4];
        float sq = (a.x * a.x + a.y * a.y) + (a.z * a.z + a.w * a.w)
                 + (c.x * c.x + c.y * c.y) + (c.z * c.z + c.w * c.w);
        float scale = sq / (1.f + sq) * rsqrtf(sq + 1e-8f);
        a.x *= scale; a.y *= scale; a.z *= scale; a.w *= scale;
        c.x *= scale; c.y *= scale; c.z *= scale; c.w *= scale;
        int l = l0 + l_loc;
        float* dst = &g_yq[((size_t)(b * L_ + l)) * NOC1 + cp * 8];
        *(float4*)dst       = a;
        *(float4*)(dst + 4) = c;
    }
}

// ---------------------------------------------------------------------------
// Kernel 2: conv2 via TENSOR CORES (m16n8k8 tf32, 3-term split) + routing.
// D[oc=256, cp=32] per (b,l); warp w owns oc [w*32, w*32+32) = 2 m-tiles.
// c-frag rows map to oc=(csa*16+asa) -> stored straight into Vs[csa][asa][cp].
// Routing (a-update/efT/sinv/squash) identical to R11.
// ---------------------------------------------------------------------------
__global__ __launch_bounds__(256) void conv2_route_kernel(
    const float* __restrict__ b2, float* __restrict__ out)
{
    __shared__ float yph[CP_][YPAD];                 // y hi-split [cp][k=24]
    __shared__ float ypl[CP_][YPAD];                 // y lo-split
    __shared__ float b2s[NOC1];
    __shared__ float efT[CSA_][EPAD];                // exp(logits) transposed
    __shared__ __align__(16) float sinv[CP_];
    __shared__ float vsh[16][16];
    __shared__ __align__(16) float Vs[16][16][VPAD]; // V [csa][asa][cp]

    const int bl = blockIdx.x;
    const int l  = bl & (L_ - 1);
    const int t  = threadIdx.x;
    const int wid   = t >> 5;
    const int lane  = t & 31;
    const int group = lane >> 2;
    const int tid4  = lane & 3;

    // Build split y panels: thread t handles (cp = t>>3, j = t&7), 3 dh rows
    {
        const float* base = g_yq + (size_t)bl * NOC1;
        const int cp_i = t >> 3, j_i = t & 7;
#pragma unroll
        for (int dh = 0; dh < 3; dh++) {
            float val = 0.f;
            if ((dh == 1) || (dh == 0 && l > 0) || (dh == 2 && l < L_ - 1))
                val = base[t + (dh - 1) * NOC1];
            float hi = t32hi(val);
            yph[cp_i][dh * 8 + j_i] = hi;
            ypl[cp_i][dh * 8 + j_i] = val - hi;
        }
        b2s[t] = b2[t];
    }
    __syncthreads();

    // c-frags: [mt][nt][4], bias-initialized (bias depends on oc row only)
    float c[2][4][4];
#pragma unroll
    for (int mt = 0; mt < 2; mt++) {
        float bv0 = b2s[wid * 32 + mt * 16 + group];
        float bv1 = b2s[wid * 32 + mt * 16 + 8 + group];
#pragma unroll
        for (int nt = 0; nt < 4; nt++) {
            c[mt][nt][0] = bv0; c[mt][nt][1] = bv0;
            c[mt][nt][2] = bv1; c[mt][nt][3] = bv1;
        }
    }

    // a-frags (w2 hi), preloaded: [mt][k]
    uint4 af[2][3];
#pragma unroll
    for (int mt = 0; mt < 2; mt++)
#pragma unroll
        for (int k = 0; k < 3; k++)
            af[mt][k] = *(const uint4*)&g_w2f[(((wid * 2 + mt)) * 3 + k) * 128 + lane * 4];

    // Terms 1,2: w_hi x y_hi, w_hi x y_lo
#pragma unroll
    for (int pass = 0; pass < 2; pass++) {
        const float (*yp)[YPAD] = pass ? ypl : yph;
#pragma unroll
        for (int k = 0; k < 3; k++)
#pragma unroll
            for (int nt = 0; nt < 4; nt++) {
                unsigned b0 = __float_as_uint(yp[nt * 8 + group][k * 8 + tid4]);
                unsigned b1 = __float_as_uint(yp[nt * 8 + group][k * 8 + tid4 + 4]);
                MMA_TF32(c[0][nt], af[0][k], b0, b1);
                MMA_TF32(c[1][nt], af[1][k], b0, b1);
            }
    }
    // Term 3: w_lo x y_hi
#pragma unroll
    for (int mt = 0; mt < 2; mt++)
#pragma unroll
        for (int k = 0; k < 3; k++)
            af[mt][k] = *(const uint4*)&g_w2f[((16 + wid * 2 + mt) * 3 + k) * 128 + lane * 4];
#pragma unroll
    for (int k = 0; k < 3; k++)
#pragma unroll
        for (int nt = 0; nt < 4; nt++) {
            unsigned b0 = __float_as_uint(yph[nt * 8 + group][k * 8 + tid4]);
            unsigned b1 = __float_as_uint(yph[nt * 8 + group][k * 8 + tid4 + 4]);
            MMA_TF32(c[0][nt], af[0][k], b0, b1);
            MMA_TF32(c[1][nt], af[1][k], b0, b1);
        }

    // Store c-frags into Vs: oc = wid*32+mt*16+row -> csa = wid*2+mt, asa = row
#pragma unroll
    for (int mt = 0; mt < 2; mt++) {
        int csaw = wid * 2 + mt;
#pragma unroll
        for (int nt = 0; nt < 4; nt++) {
            int cp0 = nt * 8 + tid4 * 2;
            *(float2*)&Vs[csaw][group][cp0]     = make_float2(c[mt][nt][0], c[mt][nt][1]);
            *(float2*)&Vs[csaw][group + 8][cp0] = make_float2(c[mt][nt][2], c[mt][nt][3]);
        }
    }
    __syncthreads();

    const int csa = t >> 4;
    const int asa = t & 15;
    const ulonglong2* Vp = (const ulonglong2*)&Vs[csa][asa][0];

    // ---- r = 0: uniform softmax ----
    float v;
    {
        const float4* vr = (const float4*)&Vs[csa][asa][0];
        float4 r0 = vr[0], r1 = vr[1], r2 = vr[2], r3 = vr[3];
        float4 r4 = vr[4], r5 = vr[5], r6 = vr[6], r7 = vr[7];
        float s0 = (r0.x + r0.y) + (r0.z + r0.w) + (r4.x + r4.y) + (r4.z + r4.w);
        float s1 = (r1.x + r1.y) + (r1.z + r1.w) + (r5.x + r5.y) + (r5.z + r5.w);
        float s2 = (r2.x + r2.y) + (r2.z + r2.w) + (r6.x + r6.y) + (r6.z + r6.w);
        float s3 = (r3.x + r3.y) + (r3.z + r3.w) + (r7.x + r7.y) + (r7.z + r7.w);
        float s = ((s0 + s1) + (s2 + s3)) * (1.f / 16.f);
        float sq = s * s;
        sq += __shfl_xor_sync(0xffffffffu, sq, 1);
        sq += __shfl_xor_sync(0xffffffffu, sq, 2);
        sq += __shfl_xor_sync(0xffffffffu, sq, 4);
        sq += __shfl_xor_sync(0xffffffffu, sq, 8);
        float scale = sq / (1.f + sq) * rsqrtf(sq + 1e-8f);
        v = s * scale;
    }
    vsh[csa][asa] = v;
    __syncthreads();

    // a-update mapping: thread owns pairs (cp_a, cs0) and (cp_a, cs0+8)
    const int cp_a = t & 31;
    const int cs0  = t >> 5;
    float blog0, blog1;
    {
        const float4* vpA = (const float4*)vsh[cs0];
        const float4* vpB = (const float4*)vsh[cs0 + 8];
        float4 vA0 = vpA[0], vA1 = vpA[1], vA2 = vpA[2], vA3 = vpA[3];
        float4 vB0 = vpB[0], vB1 = vpB[1], vB2 = vpB[2], vB3 = vpB[3];
        const float* VsA = &Vs[cs0][0][cp_a];
        const float* VsB = &Vs[cs0 + 8][0][cp_a];
        float p0, p1, q0, q1;
        p0  = VsA[0*VPAD]*vA0.x + VsA[1*VPAD]*vA0.y + VsA[2*VPAD]*vA0.z + VsA[3*VPAD]*vA0.w;
        p1  = VsA[4*VPAD]*vA1.x + VsA[5*VPAD]*vA1.y + VsA[6*VPAD]*vA1.z + VsA[7*VPAD]*vA1.w;
        p0 += VsA[8*VPAD]*vA2.x + VsA[9*VPAD]*vA2.y + VsA[10*VPAD]*vA2.z + VsA[11*VPAD]*vA2.w;
        p1 += VsA[12*VPAD]*vA3.x + VsA[13*VPAD]*vA3.y + VsA[14*VPAD]*vA3.z + VsA[15*VPAD]*vA3.w;
        q0  = VsB[0*VPAD]*vB0.x + VsB[1*VPAD]*vB0.y + VsB[2*VPAD]*vB0.z + VsB[3*VPAD]*vB0.w;
        q1  = VsB[4*VPAD]*vB1.x + VsB[5*VPAD]*vB1.y + VsB[6*VPAD]*vB1.z + VsB[7*VPAD]*vB1.w;
        q0 += VsB[8*VPAD]*vB2.x + VsB[9*VPAD]*vB2.y + VsB[10*VPAD]*vB2.z + VsB[11*VPAD]*vB2.w;
        q1 += VsB[12*VPAD]*vB3.x + VsB[13*VPAD]*vB3.y + VsB[14*VPAD]*vB3.z + VsB[15*VPAD]*vB3.w;
        blog0 = p0 + p1;
        blog1 = q0 + q1;
    }

    // ---- r = 1, 2 ----
#pragma unroll
    for (int r = 1; r < 3; r++) {
        efT[cs0][cp_a]     = __expf(blog0);
        efT[cs0 + 8][cp_a] = __expf(blog1);
        __syncthreads();
        if (t < CP_) {
            float u0 = 0.f, u1 = 0.f, u2 = 0.f, u3 = 0.f;
#pragma unroll
            for (int j2 = 0; j2 < CSA_; j2 += 4) {
                u0 += efT[j2][t];     u1 += efT[j2 + 1][t];
                u2 += efT[j2 + 2][t]; u3 += efT[j2 + 3][t];
            }
            sinv[t] = __fdividef(1.f, (u0 + u1) + (u2 + u3));
        }
        __syncthreads();

        // packed s = sum_cp efT[csa][cp]*sinv[cp]*V[cp]
        ull s2a = 0ULL, s2b = 0ULL, s2c = 0ULL, s2d = 0ULL;
        const ulonglong2* efp = (const ulonglong2*)&efT[csa][0];
        const ulonglong2* svp = (const ulonglong2*)sinv;
#pragma unroll
        for (int q = 0; q < 8; q++) {
            ulonglong2 e2 = efp[q];
            ulonglong2 n2 = svp[q];
            ulonglong2 v2 = Vp[q];
            ull p0, p1;
            MUL2(p0, e2.x, n2.x);
            MUL2(p1, e2.y, n2.y);
            if (q & 1) {
                FFMA2(s2c, p0, v2.x);
                FFMA2(s2d, p1, v2.y);
            } else {
                FFMA2(s2a, p0, v2.x);
                FFMA2(s2b, p1, v2.y);
            }
        }
        ADD2(s2a, s2a, s2b);
        ADD2(s2c, s2c, s2d);
        ADD2(s2a, s2a, s2c);
        float lo, hi;
        UNPACK2(lo, hi, s2a);
        float s = lo + hi;

        float sq = s * s;
        sq += __shfl_xor_sync(0xffffffffu, sq, 1);
        sq += __shfl_xor_sync(0xffffffffu, sq, 2);
        sq += __shfl_xor_sync(0xffffffffu, sq, 4);
        sq += __shfl_xor_sync(0xffffffffu, sq, 8);
        float scale = sq / (1.f + sq) * rsqrtf(sq + 1e-8f);
        v = s * scale;

        if (r < 2) {
            vsh[csa][asa] = v;
            __syncthreads();
            const float4* vpA = (const float4*)vsh[cs0];
            const float4* vpB = (const float4*)vsh[cs0 + 8];
            float4 vA0 = vpA[0], vA1 = vpA[1], vA2 = vpA[2], vA3 = vpA[3];
            float4 vB0 = vpB[0], vB1 = vpB[1], vB2 = vpB[2], vB3 = vpB[3];
            const float* VsA = &Vs[cs0][0][cp_a];
            const float* VsB = &Vs[cs0 + 8][0][cp_a];
            float p0, p1, q0, q1;
            p0  = VsA[0*VPAD]*vA0.x + VsA[1*VPAD]*vA0.y + VsA[2*VPAD]*vA0.z + VsA[3*VPAD]*vA0.w;
            p1  = VsA[4*VPAD]*vA1.x + VsA[5*VPAD]*vA1.y + VsA[6*VPAD]*vA1.z + VsA[7*VPAD]*vA1.w;
            p0 += VsA[8*VPAD]*vA2.x + VsA[9*VPAD]*vA2.y + VsA[10*VPAD]*vA2.z + VsA[11*VPAD]*vA2.w;
            p1 += VsA[12*VPAD]*vA3.x + VsA[13*VPAD]*vA3.y + VsA[14*VPAD]*vA3.z + VsA[15*VPAD]*vA3.w;
            q0  = VsB[0*VPAD]*vB0.x + VsB[1*VPAD]*vB0.y + VsB[2*VPAD]*vB0.z + VsB[3*VPAD]*vB0.w;
            q1  = VsB[4*VPAD]*vB1.x + VsB[5*VPAD]*vB1.y + VsB[6*VPAD]*vB1.z + VsB[7*VPAD]*vB1.w;
            q0 += VsB[8*VPAD]*vB2.x + VsB[9*VPAD]*vB2.y + VsB[10*VPAD]*vB2.z + VsB[11*VPAD]*vB2.w;
            q1 += VsB[12*VPAD]*vB3.x + VsB[13*VPAD]*vB3.y + VsB[14*VPAD]*vB3.z + VsB[15*VPAD]*vB3.w;
            blog0 += p0 + p1;
            blog1 += q0 + q1;
        }
    }

    out[(size_t)bl * 256 + t] = v;
}

// ---------------------------------------------------------------------------
extern "C" void kernel_launch(void* const* d_in, const int* in_sizes, int n_in,
                              void* d_out, int out_size)
{
    const float* x  = (const float*)d_in[0];   // [8, 64, 1024]
    const float* w1 = (const float*)d_in[1];   // [256, 64, 9]
    const float* b1 = (const float*)d_in[2];   // [256]
    const float* w2 = (const float*)d_in[3];   // [256, 1, 3, 8]
    const float* b2 = (const float*)d_in[4];   // [256]
    float* out = (float*)d_out;                // [8, 16384, 16]

    prep_kernel<<<576, 256>>>(w1, w2);
    conv1_squash_kernel<<<dim3(L_ / 16, B_), 128>>>(x, b1);
    conv2_route_kernel<<<B_ * L_, 256>>>(b2, out);
}

// round 13
// speedup vs baseline: 1.7331x; 1.3693x over previous
#include <cuda_runtime.h>

// Problem constants
#define B_    8
#define K_    64
#define L_    1024
#define CP_   32
#define CSA_  16
#define NOC1  256
#define K1    576          // K_*G2_
#define VPAD  36           // Vs cp-dim pad (16B-aligned rows)
#define EPAD  36           // efT cp-dim pad
#define YPAD  28           // yph/ypl k-dim pad

typedef unsigned long long ull;

// Packed fp32x2 helpers (sm_100+)
#define FFMA2(acc, a, b) asm("fma.rn.f32x2 %0, %1, %2, %0;" : "+l"(acc) : "l"(a), "l"(b))
#define MUL2(dst, a, b)  asm("mul.rn.f32x2 %0, %1, %2;" : "=l"(dst) : "l"(a), "l"(b))
#define ADD2(dst, a, b)  asm("add.rn.f32x2 %0, %1, %2;" : "=l"(dst) : "l"(a), "l"(b))
#define UNPACK2(lo, hi, v) asm("mov.b64 {%0, %1}, %2;" : "=f"(lo), "=f"(hi) : "l"(v))

// tf32 mma: D(16x8) += A(16x8,row) * B(8x8,col)
#define MMA_TF32(c, au, b0, b1) \
    asm("mma.sync.aligned.m16n8k8.row.col.f32.tf32.tf32.f32 " \
        "{%0,%1,%2,%3},{%4,%5,%6,%7},{%8,%9},{%0,%1,%2,%3};" \
        : "+f"((c)[0]), "+f"((c)[1]), "+f"((c)[2]), "+f"((c)[3]) \
        : "r"((au).x), "r"((au).y), "r"((au).z), "r"((au).w), "r"(b0), "r"(b1))

__device__ __forceinline__ float t32hi(float x) {
    return __uint_as_float(__float_as_uint(x) & 0xFFFFE000u);
}

// Scratch (allocation-free: device globals)
__device__ float g_yq[B_ * L_ * NOC1];       // squashed conv1 output
__device__ float g_w1f[2 * 16 * 72 * 128];   // conv1 w frags [split][mt][kc][lane*4+i]
__device__ float g_w2f[2 * 16 * 3 * 128];    // conv2 w frags

// ---------------------------------------------------------------------------
// Prep: build tf32 hi/lo weight fragments for conv1 and conv2
// ---------------------------------------------------------------------------
__global__ void prep_kernel(const float* __restrict__ w1, const float* __restrict__ w2) {
    int idx = blockIdx.x * 256 + threadIdx.x;
    if (idx < 2 * 16 * 72 * 128) {
        int i    = idx & 3;
        int lane = (idx >> 2) & 31;
        int rest = idx >> 7;            // (split*16 + mt)*72 + kc
        int kc    = rest % 72;
        int mtf   = (rest / 72) & 15;
        int split = rest / 1152;
        int group = lane >> 2, tid4 = lane & 3;
        int row = mtf * 16 + ((i & 1) << 3) + group;
        int col = kc * 8 + ((i >> 1) << 2) + tid4;
        float val = w1[row * K1 + col];
        float hi = t32hi(val);
        g_w1f[idx] = split ? (val - hi) : hi;
    }
    if (idx < 2 * 16 * 3 * 128) {
        int i    = idx & 3;
        int lane = (idx >> 2) & 31;
        int rest = idx >> 7;
        int k    = rest % 3;
        int mt   = (rest / 3) & 15;
        int split = rest / 48;
        int group = lane >> 2, tid4 = lane & 3;
        int row = ((i & 1) << 3) + group;
        int col = ((i >> 1) << 2) + tid4;
        float val = w2[(mt * 16 + row) * 24 + k * 8 + col];
        float hi = t32hi(val);
        g_w2f[idx] = split ? (val - hi) : hi;
    }
}

// ---------------------------------------------------------------------------
// Kernel 1: conv1 via TENSOR CORES (m16n8k8 tf32, 3-term split) + squash.
// Block: M=256 oc x N=32 l, 256 threads (8 warps x 2 m-tiles x 4 n-tiles).
// b-frags read from split x panels in smem with incremental (ic,tt) cursors.
// ---------------------------------------------------------------------------
__global__ __launch_bounds__(256) void conv1_mma_kernel(
    const float* __restrict__ x, const float* __restrict__ b1)
{
    __shared__ __align__(16) float sbuf[32 * 264];   // xh+xl (mainloop) / ysh (epilogue)
    __shared__ float b1s[NOC1];
    float (*xh)[48]  = (float(*)[48])sbuf;
    float (*xl)[48]  = (float(*)[48])(sbuf + 64 * 48);
    float (*ysh)[264] = (float(*)[264])sbuf;

    const int b  = blockIdx.y;
    const int l0 = blockIdx.x * 32;
    const int t  = threadIdx.x;

    b1s[t] = b1[t];
    for (int i = t; i < K_ * 40; i += 256) {
        int ic = i / 40, j = i - ic * 40;
        int l = l0 - 4 + j;
        float v = (l >= 0 && l < L_) ? x[(b * K_ + ic) * L_ + l] : 0.f;
        float hi = t32hi(v);
        xh[ic][j] = hi;
        xl[ic][j] = v - hi;
    }
    __syncthreads();

    const int wid = t >> 5, lane = t & 31;
    const int group = lane >> 2, tid4 = lane & 3;

    float c[2][4][4];
#pragma unroll
    for (int mt = 0; mt < 2; mt++)
#pragma unroll
        for (int nt = 0; nt < 4; nt++)
#pragma unroll
            for (int i = 0; i < 4; i++) c[mt][nt][i] = 0.f;

    const float* xbh = &xh[0][0];
    const float* xbl = &xl[0][0];
    const float* wf0 = g_w1f + ((wid * 2 + 0) * 72) * 128 + lane * 4;          // hi mt0
    const float* wf1 = g_w1f + ((wid * 2 + 1) * 72) * 128 + lane * 4;          // hi mt1
    const float* wg0 = g_w1f + ((16 + wid * 2 + 0) * 72) * 128 + lane * 4;     // lo mt0
    const float* wg1 = g_w1f + ((16 + wid * 2 + 1) * 72) * 128 + lane * 4;     // lo mt1

    // PASS A: b = x_hi; accumulate w_hi*x_hi and w_lo*x_hi
    {
        int tt0 = tid4,     off0 = tid4;
        int tt1 = tid4 + 4, off1 = tid4 + 4;
        for (int kc = 0; kc < 72; kc++) {
            uint4 ah0 = *(const uint4*)(wf0 + kc * 128);
            uint4 ah1 = *(const uint4*)(wf1 + kc * 128);
            uint4 al0 = *(const uint4*)(wg0 + kc * 128);
            uint4 al1 = *(const uint4*)(wg1 + kc * 128);
            unsigned bb0[4], bb1[4];
#pragma unroll
            for (int nt = 0; nt < 4; nt++) {
                bb0[nt] = __float_as_uint(xbh[off0 + nt * 8 + group]);
                bb1[nt] = __float_as_uint(xbh[off1 + nt * 8 + group]);
            }
#pragma unroll
            for (int nt = 0; nt < 4; nt++) {
                MMA_TF32(c[0][nt], ah0, bb0[nt], bb1[nt]);
                MMA_TF32(c[1][nt], ah1, bb0[nt], bb1[nt]);
            }
#pragma unroll
            for (int nt = 0; nt < 4; nt++) {
                MMA_TF32(c[0][nt], al0, bb0[nt], bb1[nt]);
                MMA_TF32(c[1][nt], al1, bb0[nt], bb1[nt]);
            }
            tt0 += 8; if (tt0 >= 9) { tt0 -= 9; off0 += 47; } else off0 += 8;
            tt1 += 8; if (tt1 >= 9) { tt1 -= 9; off1 += 47; } else off1 += 8;
        }
    }
    // PASS B: b = x_lo; accumulate w_hi*x_lo
    {
        int tt0 = tid4,     off0 = tid4;
        int tt1 = tid4 + 4, off1 = tid4 + 4;
        for (int kc = 0; kc < 72; kc++) {
            uint4 ah0 = *(const uint4*)(wf0 + kc * 128);
            uint4 ah1 = *(const uint4*)(wf1 + kc * 128);
            unsigned bb0[4], bb1[4];
#pragma unroll
            for (int nt = 0; nt < 4; nt++) {
                bb0[nt] = __float_as_uint(xbl[off0 + nt * 8 + group]);
                bb1[nt] = __float_as_uint(xbl[off1 + nt * 8 + group]);
            }
#pragma unroll
            for (int nt = 0; nt < 4; nt++) {
                MMA_TF32(c[0][nt], ah0, bb0[nt], bb1[nt]);
                MMA_TF32(c[1][nt], ah1, bb0[nt], bb1[nt]);
            }
            tt0 += 8; if (tt0 >= 9) { tt0 -= 9; off0 += 47; } else off0 += 8;
            tt1 += 8; if (tt1 >= 9) { tt1 -= 9; off1 += 47; } else off1 += 8;
        }
    }
    __syncthreads();   // all x-panel reads done before ysh overwrites sbuf

    // Store c-frags (+bias) to ysh: row -> oc, col -> l
#pragma unroll
    for (int mt = 0; mt < 2; mt++)
#pragma unroll
        for (int nt = 0; nt < 4; nt++)
#pragma unroll
            for (int i = 0; i < 4; i++) {
                int oc   = wid * 32 + mt * 16 + ((i >> 1) << 3) + group;
                int lloc = nt * 8 + tid4 * 2 + (i & 1);
                ysh[lloc][oc] = c[mt][nt][i] + b1s[oc];
            }
    __syncthreads();

    // Squash per (l, cp) 8-group, write g_yq
    for (int g = t; g < 1024; g += 256) {
        int lloc = g >> 5, cp = g & 31;
        float4 a  = *(const float4*)&ysh[lloc][cp * 8];
        float4 c4 = *(const float4*)&ysh[lloc][cp * 8 + 4];
        float sq = (a.x * a.x + a.y * a.y) + (a.z * a.z + a.w * a.w)
                 + (c4.x * c4.x + c4.y * c4.y) + (c4.z * c4.z + c4.w * c4.w);
        float scale = sq / (1.f + sq) * rsqrtf(sq + 1e-8f);
        a.x *= scale; a.y *= scale; a.z *= scale; a.w *= scale;
        c4.x *= scale; c4.y *= scale; c4.z *= scale; c4.w *= scale;
        float* dst = &g_yq[((size_t)(b * L_ + l0 + lloc)) * NOC1 + cp * 8];
        *(float4*)dst       = a;
        *(float4*)(dst + 4) = c4;
    }
}

// ---------------------------------------------------------------------------
// Kernel 2: conv2 via tensor cores + routing (R12-verified, unchanged)
// ---------------------------------------------------------------------------
__global__ __launch_bounds__(256) void conv2_route_kernel(
    const float* __restrict__ b2, float* __restrict__ out)
{
    __shared__ float yph[CP_][YPAD];
    __shared__ float ypl[CP_][YPAD];
    __shared__ float b2s[NOC1];
    __shared__ float efT[CSA_][EPAD];
    __shared__ __align__(16) float sinv[CP_];
    __shared__ float vsh[16][16];
    __shared__ __align__(16) float Vs[16][16][VPAD];

    const int bl = blockIdx.x;
    const int l  = bl & (L_ - 1);
    const int t  = threadIdx.x;
    const int wid   = t >> 5;
    const int lane  = t & 31;
    const int group = lane >> 2;
    const int tid4  = lane & 3;

    {
        const float* base = g_yq + (size_t)bl * NOC1;
        const int cp_i = t >> 3, j_i = t & 7;
#pragma unroll
        for (int dh = 0; dh < 3; dh++) {
            float val = 0.f;
            if ((dh == 1) || (dh == 0 && l > 0) || (dh == 2 && l < L_ - 1))
                val = base[t + (dh - 1) * NOC1];
            float hi = t32hi(val);
            yph[cp_i][dh * 8 + j_i] = hi;
            ypl[cp_i][dh * 8 + j_i] = val - hi;
        }
        b2s[t] = b2[t];
    }
    __syncthreads();

    float c[2][4][4];
#pragma unroll
    for (int mt = 0; mt < 2; mt++) {
        float bv0 = b2s[wid * 32 + mt * 16 + group];
        float bv1 = b2s[wid * 32 + mt * 16 + 8 + group];
#pragma unroll
        for (int nt = 0; nt < 4; nt++) {
            c[mt][nt][0] = bv0; c[mt][nt][1] = bv0;
            c[mt][nt][2] = bv1; c[mt][nt][3] = bv1;
        }
    }

    uint4 af[2][3];
#pragma unroll
    for (int mt = 0; mt < 2; mt++)
#pragma unroll
        for (int k = 0; k < 3; k++)
            af[mt][k] = *(const uint4*)&g_w2f[(((wid * 2 + mt)) * 3 + k) * 128 + lane * 4];

#pragma unroll
    for (int pass = 0; pass < 2; pass++) {
        const float (*yp)[YPAD] = pass ? ypl : yph;
#pragma unroll
        for (int k = 0; k < 3; k++)
#pragma unroll
            for (int nt = 0; nt < 4; nt++) {
                unsigned b0 = __float_as_uint(yp[nt * 8 + group][k * 8 + tid4]);
                unsigned b1 = __float_as_uint(yp[nt * 8 + group][k * 8 + tid4 + 4]);
                MMA_TF32(c[0][nt], af[0][k], b0, b1);
                MMA_TF32(c[1][nt], af[1][k], b0, b1);
            }
    }
#pragma unroll
    for (int mt = 0; mt < 2; mt++)
#pragma unroll
        for (int k = 0; k < 3; k++)
            af[mt][k] = *(const uint4*)&g_w2f[((16 + wid * 2 + mt) * 3 + k) * 128 + lane * 4];
#pragma unroll
    for (int k = 0; k < 3; k++)
#pragma unroll
        for (int nt = 0; nt < 4; nt++) {
            unsigned b0 = __float_as_uint(yph[nt * 8 + group][k * 8 + tid4]);
            unsigned b1 = __float_as_uint(yph[nt * 8 + group][k * 8 + tid4 + 4]);
            MMA_TF32(c[0][nt], af[0][k], b0, b1);
            MMA_TF32(c[1][nt], af[1][k], b0, b1);
        }

#pragma unroll
    for (int mt = 0; mt < 2; mt++) {
        int csaw = wid * 2 + mt;
#pragma unroll
        for (int nt = 0; nt < 4; nt++) {
            int cp0 = nt * 8 + tid4 * 2;
            *(float2*)&Vs[csaw][group][cp0]     = make_float2(c[mt][nt][0], c[mt][nt][1]);
            *(float2*)&Vs[csaw][group + 8][cp0] = make_float2(c[mt][nt][2], c[mt][nt][3]);
        }
    }
    __syncthreads();

    const int csa = t >> 4;
    const int asa = t & 15;
    const ulonglong2* Vp = (const ulonglong2*)&Vs[csa][asa][0];

    float v;
    {
        const float4* vr = (const float4*)&Vs[csa][asa][0];
        float4 r0 = vr[0], r1 = vr[1], r2 = vr[2], r3 = vr[3];
        float4 r4 = vr[4], r5 = vr[5], r6 = vr[6], r7 = vr[7];
        float s0 = (r0.x + r0.y) + (r0.z + r0.w) + (r4.x + r4.y) + (r4.z + r4.w);
        float s1 = (r1.x + r1.y) + (r1.z + r1.w) + (r5.x + r5.y) + (r5.z + r5.w);
        float s2 = (r2.x + r2.y) + (r2.z + r2.w) + (r6.x + r6.y) + (r6.z + r6.w);
        float s3 = (r3.x + r3.y) + (r3.z + r3.w) + (r7.x + r7.y) + (r7.z + r7.w);
        float s = ((s0 + s1) + (s2 + s3)) * (1.f / 16.f);
        float sq = s * s;
        sq += __shfl_xor_sync(0xffffffffu, sq, 1);
        sq += __shfl_xor_sync(0xffffffffu, sq, 2);
        sq += __shfl_xor_sync(0xffffffffu, sq, 4);
        sq += __shfl_xor_sync(0xffffffffu, sq, 8);
        float scale = sq / (1.f + sq) * rsqrtf(sq + 1e-8f);
        v = s * scale;
    }
    vsh[csa][asa] = v;
    __syncthreads();

    const int cp_a = t & 31;
    const int cs0  = t >> 5;
    float blog0, blog1;
    {
        const float4* vpA = (const float4*)vsh[cs0];
        const float4* vpB = (const float4*)vsh[cs0 + 8];
        float4 vA0 = vpA[0], vA1 = vpA[1], vA2 = vpA[2], vA3 = vpA[3];
        float4 vB0 = vpB[0], vB1 = vpB[1], vB2 = vpB[2], vB3 = vpB[3];
        const float* VsA = &Vs[cs0][0][cp_a];
        const float* VsB = &Vs[cs0 + 8][0][cp_a];
        float p0, p1, q0, q1;
        p0  = VsA[0*VPAD]*vA0.x + VsA[1*VPAD]*vA0.y + VsA[2*VPAD]*vA0.z + VsA[3*VPAD]*vA0.w;
        p1  = VsA[4*VPAD]*vA1.x + VsA[5*VPAD]*vA1.y + VsA[6*VPAD]*vA1.z + VsA[7*VPAD]*vA1.w;
        p0 += VsA[8*VPAD]*vA2.x + VsA[9*VPAD]*vA2.y + VsA[10*VPAD]*vA2.z + VsA[11*VPAD]*vA2.w;
        p1 += VsA[12*VPAD]*vA3.x + VsA[13*VPAD]*vA3.y + VsA[14*VPAD]*vA3.z + VsA[15*VPAD]*vA3.w;
        q0  = VsB[0*VPAD]*vB0.x + VsB[1*VPAD]*vB0.y + VsB[2*VPAD]*vB0.z + VsB[3*VPAD]*vB0.w;
        q1  = VsB[4*VPAD]*vB1.x + VsB[5*VPAD]*vB1.y + VsB[6*VPAD]*vB1.z + VsB[7*VPAD]*vB1.w;
        q0 += VsB[8*VPAD]*vB2.x + VsB[9*VPAD]*vB2.y + VsB[10*VPAD]*vB2.z + VsB[11*VPAD]*vB2.w;
        q1 += VsB[12*VPAD]*vB3.x + VsB[13*VPAD]*vB3.y + VsB[14*VPAD]*vB3.z + VsB[15*VPAD]*vB3.w;
        blog0 = p0 + p1;
        blog1 = q0 + q1;
    }

#pragma unroll
    for (int r = 1; r < 3; r++) {
        efT[cs0][cp_a]     = __expf(blog0);
        efT[cs0 + 8][cp_a] = __expf(blog1);
        __syncthreads();
        if (t < CP_) {
            float u0 = 0.f, u1 = 0.f, u2 = 0.f, u3 = 0.f;
#pragma unroll
            for (int j2 = 0; j2 < CSA_; j2 += 4) {
                u0 += efT[j2][t];     u1 += efT[j2 + 1][t];
                u2 += efT[j2 + 2][t]; u3 += efT[j2 + 3][t];
            }
            sinv[t] = __fdividef(1.f, (u0 + u1) + (u2 + u3));
        }
        __syncthreads();

        ull s2a = 0ULL, s2b = 0ULL, s2c = 0ULL, s2d = 0ULL;
        const ulonglong2* efp = (const ulonglong2*)&efT[csa][0];
        const ulonglong2* svp = (const ulonglong2*)sinv;
#pragma unroll
        for (int q = 0; q < 8; q++) {
            ulonglong2 e2 = efp[q];
            ulonglong2 n2 = svp[q];
            ulonglong2 v2 = Vp[q];
            ull p0, p1;
            MUL2(p0, e2.x, n2.x);
            MUL2(p1, e2.y, n2.y);
            if (q & 1) {
                FFMA2(s2c, p0, v2.x);
                FFMA2(s2d, p1, v2.y);
            } else {
                FFMA2(s2a, p0, v2.x);
                FFMA2(s2b, p1, v2.y);
            }
        }
        ADD2(s2a, s2a, s2b);
        ADD2(s2c, s2c, s2d);
        ADD2(s2a, s2a, s2c);
        float lo, hi;
        UNPACK2(lo, hi, s2a);
        float s = lo + hi;

        float sq = s * s;
        sq += __shfl_xor_sync(0xffffffffu, sq, 1);
        sq += __shfl_xor_sync(0xffffffffu, sq, 2);
        sq += __shfl_xor_sync(0xffffffffu, sq, 4);
        sq += __shfl_xor_sync(0xffffffffu, sq, 8);
        float scale = sq / (1.f + sq) * rsqrtf(sq + 1e-8f);
        v = s * scale;

        if (r < 2) {
            vsh[csa][asa] = v;
            __syncthreads();
            const float4* vpA = (const float4*)vsh[cs0];
            const float4* vpB = (const float4*)vsh[cs0 + 8];
            float4 vA0 = vpA[0], vA1 = vpA[1], vA2 = vpA[2], vA3 = vpA[3];
            float4 vB0 = vpB[0], vB1 = vpB[1], vB2 = vpB[2], vB3 = vpB[3];
            const float* VsA = &Vs[cs0][0][cp_a];
            const float* VsB = &Vs[cs0 + 8][0][cp_a];
            float p0, p1, q0, q1;
            p0  = VsA[0*VPAD]*vA0.x + VsA[1*VPAD]*vA0.y + VsA[2*VPAD]*vA0.z + VsA[3*VPAD]*vA0.w;
            p1  = VsA[4*VPAD]*vA1.x + VsA[5*VPAD]*vA1.y + VsA[6*VPAD]*vA1.z + VsA[7*VPAD]*vA1.w;
            p0 += VsA[8*VPAD]*vA2.x + VsA[9*VPAD]*vA2.y + VsA[10*VPAD]*vA2.z + VsA[11*VPAD]*vA2.w;
            p1 += VsA[12*VPAD]*vA3.x + VsA[13*VPAD]*vA3.y + VsA[14*VPAD]*vA3.z + VsA[15*VPAD]*vA3.w;
            q0  = VsB[0*VPAD]*vB0.x + VsB[1*VPAD]*vB0.y + VsB[2*VPAD]*vB0.z + VsB[3*VPAD]*vB0.w;
            q1  = VsB[4*VPAD]*vB1.x + VsB[5*VPAD]*vB1.y + VsB[6*VPAD]*vB1.z + VsB[7*VPAD]*vB1.w;
            q0 += VsB[8*VPAD]*vB2.x + VsB[9*VPAD]*vB2.y + VsB[10*VPAD]*vB2.z + VsB[11*VPAD]*vB2.w;
            q1 += VsB[12*VPAD]*vB3.x + VsB[13*VPAD]*vB3.y + VsB[14*VPAD]*vB3.z + VsB[15*VPAD]*vB3.w;
            blog0 += p0 + p1;
            blog1 += q0 + q1;
        }
    }

    out[(size_t)bl * 256 + t] = v;
}

// ---------------------------------------------------------------------------
extern "C" void kernel_launch(void* const* d_in, const int* in_sizes, int n_in,
                              void* d_out, int out_size)
{
    const float* x  = (const float*)d_in[0];   // [8, 64, 1024]
    const float* w1 = (const float*)d_in[1];   // [256, 64, 9]
    const float* b1 = (const float*)d_in[2];   // [256]
    const float* w2 = (const float*)d_in[3];   // [256, 1, 3, 8]
    const float* b2 = (const float*)d_in[4];   // [256]
    float* out = (float*)d_out;                // [8, 16384, 16]

    prep_kernel<<<1152, 256>>>(w1, w2);
    conv1_mma_kernel<<<dim3(L_ / 32, B_), 256>>>(x, b1);
    conv2_route_kernel<<<B_ * L_, 256>>>(b2, out);
}